// round 10
// baseline (speedup 1.0000x reference)
#include <cuda_runtime.h>
#include <cuda_bf16.h>
#include <cstdint>
#include <math.h>

// Problem constants (fixed shapes)
#define T_SEQ 2048
#define BATCH 2
#define DM    1536
#define NH    16
#define HD    96
#define QKVN  4608          // 3 * NH * HD
#define MROWS 4096          // BATCH * T_SEQ
#define NTRIP 32            // HD / 3

// scale * log2(e): fold softmax scale + exp->exp2 conversion into q
#define SCALE_LOG2E 0.14724463267f

// Scratch (device globals: no allocations allowed)
__device__ __align__(128) float g_qkv[(size_t)MROWS * QKVN];   // [b,t, 3*H*hd]  (q|k|v)

// bf16x3 split buffers (projection GEMMs)
__device__ __align__(128) __nv_bfloat16 g_xhi[(size_t)MROWS * DM];
__device__ __align__(128) __nv_bfloat16 g_xlo[(size_t)MROWS * DM];
__device__ __align__(128) __nv_bfloat16 g_wqh[(size_t)QKVN * DM];
__device__ __align__(128) __nv_bfloat16 g_wql[(size_t)QKVN * DM];
__device__ __align__(128) __nv_bfloat16 g_woh[(size_t)DM * DM];
__device__ __align__(128) __nv_bfloat16 g_wol[(size_t)DM * DM];
__device__ __align__(128) __nv_bfloat16 g_ahi[(size_t)MROWS * DM];
__device__ __align__(128) __nv_bfloat16 g_alo[(size_t)MROWS * DM];

// attention operands, per-head layout [B*H][T][96]
#define BHSZ ((size_t)BATCH * NH * T_SEQ * HD)
__device__ __align__(128) __nv_bfloat16 g_qh[BHSZ];
__device__ __align__(128) __nv_bfloat16 g_ql[BHSZ];
__device__ __align__(128) __nv_bfloat16 g_kh[BHSZ];
__device__ __align__(128) __nv_bfloat16 g_kl[BHSZ];
__device__ __align__(128) __nv_bfloat16 g_vh[BHSZ];
__device__ __align__(128) __nv_bfloat16 g_vl[BHSZ];

// ======================= helpers (base ISA only) =======================
__device__ __forceinline__ uint32_t smem_u32(const void* p) {
    uint32_t a;
    asm("{ .reg .u64 t; cvta.to.shared.u64 t, %1; cvt.u32.u64 %0, t; }" : "=r"(a) : "l"(p));
    return a;
}

__device__ __forceinline__ void cp16(uint32_t saddr, const void* gptr) {
    asm volatile("cp.async.cg.shared.global [%0], [%1], 16;" :: "r"(saddr), "l"(gptr));
}
__device__ __forceinline__ void cp_commit() { asm volatile("cp.async.commit_group;"); }
__device__ __forceinline__ void cp_wait0()  { asm volatile("cp.async.wait_group 0;" ::: "memory"); }
__device__ __forceinline__ void cp_wait1()  { asm volatile("cp.async.wait_group 1;" ::: "memory"); }

__device__ __forceinline__ void ldsm4(uint32_t* r, uint32_t addr) {
    asm volatile("ldmatrix.sync.aligned.m8n8.x4.shared.b16 {%0,%1,%2,%3}, [%4];"
                 : "=r"(r[0]), "=r"(r[1]), "=r"(r[2]), "=r"(r[3]) : "r"(addr));
}
__device__ __forceinline__ void ldsm4t(uint32_t* r, uint32_t addr) {
    asm volatile("ldmatrix.sync.aligned.m8n8.x4.trans.shared.b16 {%0,%1,%2,%3}, [%4];"
                 : "=r"(r[0]), "=r"(r[1]), "=r"(r[2]), "=r"(r[3]) : "r"(addr));
}

__device__ __forceinline__ void mma16816(float* c, const uint32_t* a, uint32_t b0, uint32_t b1) {
    asm volatile(
        "mma.sync.aligned.m16n8k16.row.col.f32.bf16.bf16.f32 "
        "{%0,%1,%2,%3}, {%4,%5,%6,%7}, {%8,%9}, {%0,%1,%2,%3};"
        : "+f"(c[0]), "+f"(c[1]), "+f"(c[2]), "+f"(c[3])
        : "r"(a[0]), "r"(a[1]), "r"(a[2]), "r"(a[3]), "r"(b0), "r"(b1));
}

__device__ __forceinline__ float ex2f(float x) {
    float y;
    asm("ex2.approx.f32 %0, %1;" : "=f"(y) : "f"(x));
    return y;
}

// ======================= bf16x3 HMMA GEMM v2b: 3-stage ring, pass-major, stride 40 ==========
// NOTE: row stride MUST be 80 bytes (multiple of 16 for cp.async/ldmatrix alignment) and
// conflict-free: offsets mod 128B = {0,80,32,112,64,16,96,48}.
#define GT_STRIDE 40                       // elems per smem row (80B)
#define GT_TILE (128 * GT_STRIDE)          // elems per 128x32 tile buffer
#define GT_STAGE (4 * GT_TILE)             // Ah | Al | Bh | Bl  (elems)
#define GT_STAGE_B (GT_STAGE * 2)          // 40960 bytes
#define GEMM_SMEM (3 * GT_STAGE_B)         // 122880 bytes (3-stage ring, 1 CTA/SM)

__device__ __forceinline__ void issue_chunk(uint32_t sbase, int stage,
                                            const __nv_bfloat16* Ahi, const __nv_bfloat16* Alo,
                                            const __nv_bfloat16* Bhi, const __nv_bfloat16* Blo,
                                            int K, int m0, int n0, int col0, int tid) {
    uint32_t st = sbase + (uint32_t)stage * GT_STAGE_B;
    const __nv_bfloat16* srcs[4] = {Ahi, Alo, Bhi, Blo};
    int bases[4] = {m0, m0, n0, n0};
#pragma unroll
    for (int t = 0; t < 4; t++) {
#pragma unroll
        for (int i = 0; i < 2; i++) {
            int e = tid + i * 256;
            int q = e >> 7;                  // 0..3: 16B chunk along K
            int row = e & 127;
            uint32_t saddr = st + (uint32_t)(t * GT_TILE + row * GT_STRIDE + q * 8) * 2;
            cp16(saddr, srcs[t] + (size_t)(bases[t] + row) * K + col0 + q * 8);
        }
    }
}

__global__ __launch_bounds__(256, 1) void gemm_hmma3(const __nv_bfloat16* __restrict__ Ahi,
                                                     const __nv_bfloat16* __restrict__ Alo,
                                                     const __nv_bfloat16* __restrict__ Bhi,
                                                     const __nv_bfloat16* __restrict__ Blo,
                                                     float* __restrict__ C,
                                                     int M, int N, int K) {
    extern __shared__ __align__(128) char smem[];
    const uint32_t sbase = smem_u32(smem);
    const int tid = threadIdx.x;
    const int wid = tid >> 5;
    const int lane = tid & 31;
    const int wm = wid & 1;
    const int wn = wid >> 1;
    const int m0 = blockIdx.y * 128;
    const int n0 = blockIdx.x * 128;
    const int nchunk = K / 32;

    float acc[4][4][4];
#pragma unroll
    for (int i = 0; i < 4; i++)
#pragma unroll
        for (int j = 0; j < 4; j++)
#pragma unroll
            for (int q = 0; q < 4; q++) acc[i][j][q] = 0.0f;

    const int ar  = lane & 15;
    const int akb = (lane >> 4) << 3;
    const int br  = (lane & 7) + ((lane >> 4) << 3);
    const int bkb = ((lane >> 3) & 1) << 3;

    // prologue: fill stages 0 and 1
    issue_chunk(sbase, 0, Ahi, Alo, Bhi, Blo, K, m0, n0, 0, tid);
    cp_commit();
    issue_chunk(sbase, 1, Ahi, Alo, Bhi, Blo, K, m0, n0, 32, tid);
    cp_commit();

    for (int c = 0; c < nchunk; c++) {
        if (c + 1 < nchunk) cp_wait1(); else cp_wait0();   // stage c landed
        __syncthreads();
        if (c + 2 < nchunk) {
            // stage (c+2)%3 == (c-1)%3: consumed before the barrier above -> safe
            issue_chunk(sbase, (c + 2) % 3, Ahi, Alo, Bhi, Blo, K, m0, n0, (c + 2) * 32, tid);
            cp_commit();
        }
        const uint32_t st = sbase + (uint32_t)(c % 3) * GT_STAGE_B;
#pragma unroll
        for (int ks = 0; ks < 2; ks++) {
            uint32_t ah[4][4], al[4][4], bh[2][4], bl[2][4];
#pragma unroll
            for (int i = 0; i < 4; i++) {
                uint32_t ro = (uint32_t)((wm * 64 + i * 16 + ar) * GT_STRIDE + ks * 16 + akb) * 2;
                ldsm4(ah[i], st + ro);
                ldsm4(al[i], st + (uint32_t)GT_TILE * 2 + ro);
            }
#pragma unroll
            for (int p = 0; p < 2; p++) {
                uint32_t ro = (uint32_t)((wn * 32 + p * 16 + br) * GT_STRIDE + ks * 16 + bkb) * 2;
                ldsm4(bh[p], st + (uint32_t)GT_TILE * 4 + ro);
                ldsm4(bl[p], st + (uint32_t)GT_TILE * 6 + ro);
            }
            // pass-major: same-accumulator MMAs spaced 16 apart
#pragma unroll
            for (int i = 0; i < 4; i++)
#pragma unroll
                for (int j = 0; j < 4; j++)
                    mma16816(acc[i][j], ah[i], bh[j >> 1][(j & 1) * 2], bh[j >> 1][(j & 1) * 2 + 1]);
#pragma unroll
            for (int i = 0; i < 4; i++)
#pragma unroll
                for (int j = 0; j < 4; j++)
                    mma16816(acc[i][j], ah[i], bl[j >> 1][(j & 1) * 2], bl[j >> 1][(j & 1) * 2 + 1]);
#pragma unroll
            for (int i = 0; i < 4; i++)
#pragma unroll
                for (int j = 0; j < 4; j++)
                    mma16816(acc[i][j], al[i], bh[j >> 1][(j & 1) * 2], bh[j >> 1][(j & 1) * 2 + 1]);
        }
    }

    const int er = lane >> 2;
    const int ec = (lane & 3) * 2;
#pragma unroll
    for (int i = 0; i < 4; i++) {
        int r0 = m0 + wm * 64 + i * 16 + er;
#pragma unroll
        for (int j = 0; j < 4; j++) {
            int cc = n0 + wn * 32 + j * 8 + ec;
            *(float2*)(C + (size_t)r0 * N + cc)       = make_float2(acc[i][j][0], acc[i][j][1]);
            *(float2*)(C + (size_t)(r0 + 8) * N + cc) = make_float2(acc[i][j][2], acc[i][j][3]);
        }
    }
}

// ======================= fp32 -> bf16 hi/lo split (vectorized x4) =======================
__global__ __launch_bounds__(256) void split_bf16(const float* __restrict__ x,
                                                  __nv_bfloat16* __restrict__ hi,
                                                  __nv_bfloat16* __restrict__ lo, int n4) {
    int i = blockIdx.x * blockDim.x + threadIdx.x;
    if (i >= n4) return;
    float4 v = ((const float4*)x)[i];
    __nv_bfloat162 h01 = __floats2bfloat162_rn(v.x, v.y);
    __nv_bfloat162 h23 = __floats2bfloat162_rn(v.z, v.w);
    __nv_bfloat162 l01 = __floats2bfloat162_rn(v.x - __low2float(h01), v.y - __high2float(h01));
    __nv_bfloat162 l23 = __floats2bfloat162_rn(v.z - __low2float(h23), v.w - __high2float(h23));
    ((uint2*)hi)[i] = make_uint2(*(uint32_t*)&h01, *(uint32_t*)&h23);
    ((uint2*)lo)[i] = make_uint2(*(uint32_t*)&l01, *(uint32_t*)&l23);
}

// ======================= prep: RoPE + scale + split + per-head relayout ==================
__global__ __launch_bounds__(256) void prep_kernel(const float* __restrict__ qkv,
                                                   const float* __restrict__ Rs,
                                                   __nv_bfloat16* __restrict__ qh,
                                                   __nv_bfloat16* __restrict__ ql,
                                                   __nv_bfloat16* __restrict__ kh,
                                                   __nv_bfloat16* __restrict__ kl,
                                                   __nv_bfloat16* __restrict__ vh,
                                                   __nv_bfloat16* __restrict__ vl) {
    __shared__ float sR[NTRIP * 9];
    const int t = blockIdx.x;
    const int b = blockIdx.y;
    const int tid = threadIdx.x;

    for (int i = tid; i < NTRIP * 9; i += 256)
        sR[i] = Rs[(size_t)t * NTRIP * 9 + i];
    __syncthreads();

    const float* row = qkv + (size_t)(b * T_SEQ + t) * QKVN;

    for (int task = tid; task < 2 * NH * NTRIP; task += 256) {
        int trip = task & 31;
        int h = (task >> 5) & 15;
        int which = task >> 9;
        const float* src = row + which * (NH * HD) + h * HD + trip * 3;
        const float* R = sR + trip * 9;
        float x0 = src[0], x1 = src[1], x2 = src[2];
        float y0 = R[0] * x0 + R[1] * x1 + R[2] * x2;
        float y1 = R[3] * x0 + R[4] * x1 + R[5] * x2;
        float y2 = R[6] * x0 + R[7] * x1 + R[8] * x2;
        if (which == 0) { y0 *= SCALE_LOG2E; y1 *= SCALE_LOG2E; y2 *= SCALE_LOG2E; }
        size_t dst = ((size_t)(b * NH + h) * T_SEQ + t) * HD + trip * 3;
        __nv_bfloat16* H = which ? kh : qh;
        __nv_bfloat16* L = which ? kl : ql;
        __nv_bfloat16 h0 = __float2bfloat16(y0);
        __nv_bfloat16 h1 = __float2bfloat16(y1);
        __nv_bfloat16 h2 = __float2bfloat16(y2);
        H[dst + 0] = h0; L[dst + 0] = __float2bfloat16(y0 - __bfloat162float(h0));
        H[dst + 1] = h1; L[dst + 1] = __float2bfloat16(y1 - __bfloat162float(h1));
        H[dst + 2] = h2; L[dst + 2] = __float2bfloat16(y2 - __bfloat162float(h2));
    }

    for (int d = tid; d < NH * HD; d += 256) {
        int h = d / HD, dd = d % HD;
        float v = row[2 * NH * HD + d];
        size_t dst = ((size_t)(b * NH + h) * T_SEQ + t) * HD + dd;
        __nv_bfloat16 hv = __float2bfloat16(v);
        vh[dst] = hv;
        vl[dst] = __float2bfloat16(v - __bfloat162float(hv));
    }
}

// ======================= HMMA flash attention (bf16x3 compensated) ===============
#define AT_STR 104
#define SQH 0
#define SQL (128 * AT_STR * 2)
#define SKH (2 * 128 * AT_STR * 2)
#define SKL (SKH + 64 * AT_STR * 2)
#define SVH (SKL + 64 * AT_STR * 2)
#define SVL (SVH + 64 * AT_STR * 2)
#define ATT_SMEM (SVL + 64 * AT_STR * 2)

__global__ __launch_bounds__(256) void attn_hmma(const __nv_bfloat16* __restrict__ qh,
                                                 const __nv_bfloat16* __restrict__ ql,
                                                 const __nv_bfloat16* __restrict__ kh,
                                                 const __nv_bfloat16* __restrict__ kl,
                                                 const __nv_bfloat16* __restrict__ vh,
                                                 const __nv_bfloat16* __restrict__ vl,
                                                 __nv_bfloat16* __restrict__ ahi,
                                                 __nv_bfloat16* __restrict__ alo) {
    extern __shared__ __align__(128) char smem[];
    const uint32_t sbase = smem_u32(smem);
    const int tid = threadIdx.x;
    const int wid = tid >> 5;
    const int lane = tid & 31;
    const int qt = gridDim.x - 1 - blockIdx.x;
    const int bh = blockIdx.y;
    const int b = bh >> 4;
    const int h = bh & 15;
    const int q0 = qt * 128;

    const size_t bhoff = (size_t)bh * T_SEQ * HD;
    const __nv_bfloat16* qh_b = qh + bhoff;
    const __nv_bfloat16* ql_b = ql + bhoff;
    const __nv_bfloat16* kh_b = kh + bhoff;
    const __nv_bfloat16* kl_b = kl + bhoff;
    const __nv_bfloat16* vh_b = vh + bhoff;
    const __nv_bfloat16* vl_b = vl + bhoff;

#pragma unroll
    for (int i = 0; i < 6; i++) {
        int e = tid + i * 256;
        int row = e / 12, c = e % 12;
        uint32_t so = (uint32_t)(row * AT_STR + c * 8) * 2;
        size_t go = (size_t)(q0 + row) * HD + c * 8;
        cp16(sbase + SQH + so, qh_b + go);
        cp16(sbase + SQL + so, ql_b + go);
    }
    cp_commit();

    const int ar  = lane & 15;
    const int akb = (lane >> 4) << 3;
    const int br  = (lane & 7) + ((lane >> 4) << 3);
    const int bkb = ((lane >> 3) & 1) << 3;
    const int vr  = (lane & 7) + (((lane >> 3) & 1) << 3);
    const int vcb = ((lane >> 4) & 1) << 3;

    float oacc[12][4];
#pragma unroll
    for (int j = 0; j < 12; j++)
#pragma unroll
        for (int q = 0; q < 4; q++) oacc[j][q] = 0.0f;
    float m0r = -1e30f, m1r = -1e30f, l0r = 0.0f, l1r = 0.0f;

    const int ktiles = 2 * (qt + 1);
    const int r0loc = lane >> 2;
    const int qrow0 = q0 + wid * 16 + r0loc;
    const int qrow1 = qrow0 + 8;

    cp_wait0();
    __syncthreads();

    for (int kt = 0; kt < ktiles; kt++) {
        __syncthreads();
#pragma unroll
        for (int i = 0; i < 3; i++) {
            int e = tid + i * 256;
            int row = e / 12, c = e % 12;
            uint32_t so = (uint32_t)(row * AT_STR + c * 8) * 2;
            size_t go = (size_t)(kt * 64 + row) * HD + c * 8;
            cp16(sbase + SKH + so, kh_b + go);
            cp16(sbase + SKL + so, kl_b + go);
            cp16(sbase + SVH + so, vh_b + go);
            cp16(sbase + SVL + so, vl_b + go);
        }
        cp_commit();
        cp_wait0();
        __syncthreads();

        float sacc[8][4];
#pragma unroll
        for (int j = 0; j < 8; j++)
#pragma unroll
            for (int q = 0; q < 4; q++) sacc[j][q] = 0.0f;

#pragma unroll
        for (int t = 0; t < 6; t++) {
            uint32_t qa_h[4], qa_l[4];
            uint32_t qo = (uint32_t)((wid * 16 + ar) * AT_STR + t * 16 + akb) * 2;
            ldsm4(qa_h, sbase + SQH + qo);
            ldsm4(qa_l, sbase + SQL + qo);
#pragma unroll
            for (int g = 0; g < 4; g++) {
                uint32_t kb_h[4], kb_l[4];
                uint32_t ko = (uint32_t)((g * 16 + br) * AT_STR + t * 16 + bkb) * 2;
                ldsm4(kb_h, sbase + SKH + ko);
                ldsm4(kb_l, sbase + SKL + ko);
#pragma unroll
                for (int j2 = 0; j2 < 2; j2++) {
                    int j = g * 2 + j2;
                    mma16816(sacc[j], qa_h, kb_h[j2 * 2], kb_h[j2 * 2 + 1]);
                    mma16816(sacc[j], qa_h, kb_l[j2 * 2], kb_l[j2 * 2 + 1]);
                    mma16816(sacc[j], qa_l, kb_h[j2 * 2], kb_h[j2 * 2 + 1]);
                }
            }
        }

        if (kt >= ktiles - 2) {
            int kbase = kt * 64 + (lane & 3) * 2;
#pragma unroll
            for (int j = 0; j < 8; j++) {
                int k0i = kbase + j * 8;
                if (k0i > qrow0)     sacc[j][0] = -1e30f;
                if (k0i + 1 > qrow0) sacc[j][1] = -1e30f;
                if (k0i > qrow1)     sacc[j][2] = -1e30f;
                if (k0i + 1 > qrow1) sacc[j][3] = -1e30f;
            }
        }

        float mx0 = -1e30f, mx1 = -1e30f;
#pragma unroll
        for (int j = 0; j < 8; j++) {
            mx0 = fmaxf(mx0, fmaxf(sacc[j][0], sacc[j][1]));
            mx1 = fmaxf(mx1, fmaxf(sacc[j][2], sacc[j][3]));
        }
        mx0 = fmaxf(mx0, __shfl_xor_sync(0xffffffffu, mx0, 1));
        mx0 = fmaxf(mx0, __shfl_xor_sync(0xffffffffu, mx0, 2));
        mx1 = fmaxf(mx1, __shfl_xor_sync(0xffffffffu, mx1, 1));
        mx1 = fmaxf(mx1, __shfl_xor_sync(0xffffffffu, mx1, 2));
        float mn0 = fmaxf(m0r, mx0), mn1 = fmaxf(m1r, mx1);
        float corr0 = ex2f(m0r - mn0), corr1 = ex2f(m1r - mn1);
        m0r = mn0; m1r = mn1;

        uint32_t pa_h[8][2], pa_l[8][2];
        float rs0 = 0.0f, rs1 = 0.0f;
#pragma unroll
        for (int j = 0; j < 8; j++) {
            float p0 = ex2f(sacc[j][0] - mn0);
            float p1 = ex2f(sacc[j][1] - mn0);
            float p2 = ex2f(sacc[j][2] - mn1);
            float p3 = ex2f(sacc[j][3] - mn1);
            rs0 += p0 + p1; rs1 += p2 + p3;
            __nv_bfloat162 h01 = __floats2bfloat162_rn(p0, p1);
            __nv_bfloat162 h23 = __floats2bfloat162_rn(p2, p3);
            pa_h[j][0] = *(uint32_t*)&h01;
            pa_h[j][1] = *(uint32_t*)&h23;
            __nv_bfloat162 l01 = __floats2bfloat162_rn(p0 - __low2float(h01), p1 - __high2float(h01));
            __nv_bfloat162 l23 = __floats2bfloat162_rn(p2 - __low2float(h23), p3 - __high2float(h23));
            pa_l[j][0] = *(uint32_t*)&l01;
            pa_l[j][1] = *(uint32_t*)&l23;
        }
        rs0 += __shfl_xor_sync(0xffffffffu, rs0, 1);
        rs0 += __shfl_xor_sync(0xffffffffu, rs0, 2);
        rs1 += __shfl_xor_sync(0xffffffffu, rs1, 1);
        rs1 += __shfl_xor_sync(0xffffffffu, rs1, 2);
        l0r = l0r * corr0 + rs0;
        l1r = l1r * corr1 + rs1;
#pragma unroll
        for (int j = 0; j < 12; j++) {
            oacc[j][0] *= corr0; oacc[j][1] *= corr0;
            oacc[j][2] *= corr1; oacc[j][3] *= corr1;
        }

#pragma unroll
        for (int kc = 0; kc < 4; kc++) {
            uint32_t a_h[4] = {pa_h[2 * kc][0], pa_h[2 * kc][1], pa_h[2 * kc + 1][0], pa_h[2 * kc + 1][1]};
            uint32_t a_l[4] = {pa_l[2 * kc][0], pa_l[2 * kc][1], pa_l[2 * kc + 1][0], pa_l[2 * kc + 1][1]};
            uint32_t vrow = (uint32_t)(kc * 16 + vr);
#pragma unroll
            for (int g = 0; g < 6; g++) {
                uint32_t vb_h[4], vb_l[4];
                uint32_t vo = (vrow * AT_STR + g * 16 + vcb) * 2;
                ldsm4t(vb_h, sbase + SVH + vo);
                ldsm4t(vb_l, sbase + SVL + vo);
#pragma unroll
                for (int j2 = 0; j2 < 2; j2++) {
                    int jt = g * 2 + j2;
                    mma16816(oacc[jt], a_h, vb_h[j2 * 2], vb_h[j2 * 2 + 1]);
                    mma16816(oacc[jt], a_h, vb_l[j2 * 2], vb_l[j2 * 2 + 1]);
                    mma16816(oacc[jt], a_l, vb_h[j2 * 2], vb_h[j2 * 2 + 1]);
                }
            }
        }
    }

    float inv0 = 1.0f / l0r, inv1 = 1.0f / l1r;
    size_t base0 = (size_t)(b * T_SEQ + qrow0) * DM + h * HD;
    size_t base1 = (size_t)(b * T_SEQ + qrow1) * DM + h * HD;
#pragma unroll
    for (int j = 0; j < 12; j++) {
        int col = j * 8 + (lane & 3) * 2;
        float v0 = oacc[j][0] * inv0, v1 = oacc[j][1] * inv0;
        float v2 = oacc[j][2] * inv1, v3 = oacc[j][3] * inv1;
        __nv_bfloat162 h01 = __floats2bfloat162_rn(v0, v1);
        __nv_bfloat162 h23 = __floats2bfloat162_rn(v2, v3);
        *(__nv_bfloat162*)(ahi + base0 + col) = h01;
        *(__nv_bfloat162*)(ahi + base1 + col) = h23;
        __nv_bfloat162 l01 = __floats2bfloat162_rn(v0 - __low2float(h01), v1 - __high2float(h01));
        __nv_bfloat162 l23 = __floats2bfloat162_rn(v2 - __low2float(h23), v3 - __high2float(h23));
        *(__nv_bfloat162*)(alo + base0 + col) = l01;
        *(__nv_bfloat162*)(alo + base1 + col) = l23;
    }
}

// ======================= launch =======================
extern "C" void kernel_launch(void* const* d_in, const int* in_sizes, int n_in,
                              void* d_out, int out_size) {
    const float* x     = (const float*)d_in[0];
    const float* w_qkv = (const float*)d_in[1];
    const float* w_o   = (const float*)d_in[2];
    const float* Rs    = (const float*)d_in[3];
    float* out = (float*)d_out;

    float* qkv;
    cudaGetSymbolAddress((void**)&qkv, g_qkv);
    __nv_bfloat16 *xhi, *xlo, *wqh, *wql, *woh, *wol, *ahi, *alo;
    cudaGetSymbolAddress((void**)&xhi, g_xhi);
    cudaGetSymbolAddress((void**)&xlo, g_xlo);
    cudaGetSymbolAddress((void**)&wqh, g_wqh);
    cudaGetSymbolAddress((void**)&wql, g_wql);
    cudaGetSymbolAddress((void**)&woh, g_woh);
    cudaGetSymbolAddress((void**)&wol, g_wol);
    cudaGetSymbolAddress((void**)&ahi, g_ahi);
    cudaGetSymbolAddress((void**)&alo, g_alo);
    __nv_bfloat16 *qh, *ql, *kh, *kl, *vh, *vl;
    cudaGetSymbolAddress((void**)&qh, g_qh);
    cudaGetSymbolAddress((void**)&ql, g_ql);
    cudaGetSymbolAddress((void**)&kh, g_kh);
    cudaGetSymbolAddress((void**)&kl, g_kl);
    cudaGetSymbolAddress((void**)&vh, g_vh);
    cudaGetSymbolAddress((void**)&vl, g_vl);

    // 0) bf16 hi/lo splits (vectorized x4)
    {
        int n1 = MROWS * DM / 4, n2 = QKVN * DM / 4, n3 = DM * DM / 4;
        split_bf16<<<(n1 + 255) / 256, 256>>>(x, xhi, xlo, n1);
        split_bf16<<<(n2 + 255) / 256, 256>>>(w_qkv, wqh, wql, n2);
        split_bf16<<<(n3 + 255) / 256, 256>>>(w_o, woh, wol, n3);
    }

    // 1) QKV projection
    cudaFuncSetAttribute(gemm_hmma3, cudaFuncAttributeMaxDynamicSharedMemorySize, GEMM_SMEM);
    gemm_hmma3<<<dim3(QKVN / 128, MROWS / 128), 256, GEMM_SMEM>>>(
        xhi, xlo, wqh, wql, qkv, MROWS, QKVN, DM);

    // 2) RoPE + scale + split + per-head relayout
    prep_kernel<<<dim3(T_SEQ, BATCH), 256>>>(qkv, Rs, qh, ql, kh, kl, vh, vl);

    // 3) HMMA flash attention -> ahi/alo
    cudaFuncSetAttribute(attn_hmma, cudaFuncAttributeMaxDynamicSharedMemorySize, ATT_SMEM);
    attn_hmma<<<dim3(T_SEQ / 128, BATCH * NH), 256, ATT_SMEM>>>(
        qh, ql, kh, kl, vh, vl, ahi, alo);

    // 4) Out-projection
    gemm_hmma3<<<dim3(DM / 128, MROWS / 128), 256, GEMM_SMEM>>>(
        ahi, alo, woh, wol, out, MROWS, DM, DM);
}

// round 11
// speedup vs baseline: 1.1643x; 1.1643x over previous
#include <cuda_runtime.h>
#include <cuda_bf16.h>
#include <cstdint>
#include <math.h>

// Problem constants (fixed shapes)
#define T_SEQ 2048
#define BATCH 2
#define DM    1536
#define NH    16
#define HD    96
#define QKVN  4608          // 3 * NH * HD
#define MROWS 4096          // BATCH * T_SEQ
#define NTRIP 32            // HD / 3

// scale * log2(e): fold softmax scale + exp->exp2 conversion into q
#define SCALE_LOG2E 0.14724463267f

// Scratch (device globals: no allocations allowed)
__device__ __align__(128) float g_qkv[(size_t)MROWS * QKVN];

__device__ __align__(128) __nv_bfloat16 g_xhi[(size_t)MROWS * DM];
__device__ __align__(128) __nv_bfloat16 g_xlo[(size_t)MROWS * DM];
__device__ __align__(128) __nv_bfloat16 g_wqh[(size_t)QKVN * DM];
__device__ __align__(128) __nv_bfloat16 g_wql[(size_t)QKVN * DM];
__device__ __align__(128) __nv_bfloat16 g_woh[(size_t)DM * DM];
__device__ __align__(128) __nv_bfloat16 g_wol[(size_t)DM * DM];
__device__ __align__(128) __nv_bfloat16 g_ahi[(size_t)MROWS * DM];
__device__ __align__(128) __nv_bfloat16 g_alo[(size_t)MROWS * DM];

#define BHSZ ((size_t)BATCH * NH * T_SEQ * HD)
__device__ __align__(128) __nv_bfloat16 g_qh[BHSZ];
__device__ __align__(128) __nv_bfloat16 g_ql[BHSZ];
__device__ __align__(128) __nv_bfloat16 g_kh[BHSZ];
__device__ __align__(128) __nv_bfloat16 g_kl[BHSZ];
__device__ __align__(128) __nv_bfloat16 g_vh[BHSZ];
__device__ __align__(128) __nv_bfloat16 g_vl[BHSZ];

// ======================= helpers (base ISA only) =======================
__device__ __forceinline__ uint32_t smem_u32(const void* p) {
    uint32_t a;
    asm("{ .reg .u64 t; cvta.to.shared.u64 t, %1; cvt.u32.u64 %0, t; }" : "=r"(a) : "l"(p));
    return a;
}

__device__ __forceinline__ void cp16(uint32_t saddr, const void* gptr) {
    asm volatile("cp.async.cg.shared.global [%0], [%1], 16;" :: "r"(saddr), "l"(gptr));
}
__device__ __forceinline__ void cp_commit() { asm volatile("cp.async.commit_group;"); }
__device__ __forceinline__ void cp_wait0()  { asm volatile("cp.async.wait_group 0;" ::: "memory"); }
__device__ __forceinline__ void cp_wait1()  { asm volatile("cp.async.wait_group 1;" ::: "memory"); }

__device__ __forceinline__ void ldsm4(uint32_t* r, uint32_t addr) {
    asm volatile("ldmatrix.sync.aligned.m8n8.x4.shared.b16 {%0,%1,%2,%3}, [%4];"
                 : "=r"(r[0]), "=r"(r[1]), "=r"(r[2]), "=r"(r[3]) : "r"(addr));
}
__device__ __forceinline__ void ldsm4t(uint32_t* r, uint32_t addr) {
    asm volatile("ldmatrix.sync.aligned.m8n8.x4.trans.shared.b16 {%0,%1,%2,%3}, [%4];"
                 : "=r"(r[0]), "=r"(r[1]), "=r"(r[2]), "=r"(r[3]) : "r"(addr));
}

__device__ __forceinline__ void mma16816(float* c, const uint32_t* a, uint32_t b0, uint32_t b1) {
    asm volatile(
        "mma.sync.aligned.m16n8k16.row.col.f32.bf16.bf16.f32 "
        "{%0,%1,%2,%3}, {%4,%5,%6,%7}, {%8,%9}, {%0,%1,%2,%3};"
        : "+f"(c[0]), "+f"(c[1]), "+f"(c[2]), "+f"(c[3])
        : "r"(a[0]), "r"(a[1]), "r"(a[2]), "r"(a[3]), "r"(b0), "r"(b1));
}

__device__ __forceinline__ float ex2f(float x) {
    float y;
    asm("ex2.approx.f32 %0, %1;" : "=f"(y) : "f"(x));
    return y;
}

// ======================= bf16x3 HMMA GEMM (R5 config: 2-stage, 2 CTA/SM) + pass-major ======
#define GT_STRIDE 40                       // 80B rows: 16B-aligned, conflict-free
#define GT_TILE (128 * GT_STRIDE)
#define GT_STAGE (4 * GT_TILE)             // Ah | Al | Bh | Bl
#define GT_STAGE_B (GT_STAGE * 2)          // 40960 bytes
#define GEMM_SMEM (2 * GT_STAGE_B)         // 81920 bytes -> 2 CTAs/SM

__device__ __forceinline__ void issue_chunk(uint32_t sbase, int stage,
                                            const __nv_bfloat16* Ahi, const __nv_bfloat16* Alo,
                                            const __nv_bfloat16* Bhi, const __nv_bfloat16* Blo,
                                            int K, int m0, int n0, int col0, int tid) {
    uint32_t st = sbase + (uint32_t)stage * GT_STAGE_B;
    const __nv_bfloat16* srcs[4] = {Ahi, Alo, Bhi, Blo};
    int bases[4] = {m0, m0, n0, n0};
#pragma unroll
    for (int t = 0; t < 4; t++) {
#pragma unroll
        for (int i = 0; i < 2; i++) {
            int e = tid + i * 256;
            int q = e >> 7;
            int row = e & 127;
            uint32_t saddr = st + (uint32_t)(t * GT_TILE + row * GT_STRIDE + q * 8) * 2;
            cp16(saddr, srcs[t] + (size_t)(bases[t] + row) * K + col0 + q * 8);
        }
    }
}

__global__ __launch_bounds__(256, 2) void gemm_hmma3(const __nv_bfloat16* __restrict__ Ahi,
                                                     const __nv_bfloat16* __restrict__ Alo,
                                                     const __nv_bfloat16* __restrict__ Bhi,
                                                     const __nv_bfloat16* __restrict__ Blo,
                                                     float* __restrict__ C,
                                                     int M, int N, int K) {
    extern __shared__ __align__(128) char smem[];
    const uint32_t sbase = smem_u32(smem);
    const int tid = threadIdx.x;
    const int wid = tid >> 5;
    const int lane = tid & 31;
    const int wm = wid & 1;
    const int wn = wid >> 1;
    const int m0 = blockIdx.y * 128;
    const int n0 = blockIdx.x * 128;
    const int nchunk = K / 32;

    float acc[4][4][4];
#pragma unroll
    for (int i = 0; i < 4; i++)
#pragma unroll
        for (int j = 0; j < 4; j++)
#pragma unroll
            for (int q = 0; q < 4; q++) acc[i][j][q] = 0.0f;

    const int ar  = lane & 15;
    const int akb = (lane >> 4) << 3;
    const int br  = (lane & 7) + ((lane >> 4) << 3);
    const int bkb = ((lane >> 3) & 1) << 3;

    issue_chunk(sbase, 0, Ahi, Alo, Bhi, Blo, K, m0, n0, 0, tid);
    cp_commit();
    cp_wait0();
    __syncthreads();

    for (int c = 0; c < nchunk; c++) {
        if (c + 1 < nchunk) {
            issue_chunk(sbase, (c + 1) & 1, Ahi, Alo, Bhi, Blo, K, m0, n0, (c + 1) * 32, tid);
            cp_commit();
        }
        const uint32_t st = sbase + (uint32_t)(c & 1) * GT_STAGE_B;
#pragma unroll
        for (int ks = 0; ks < 2; ks++) {
            uint32_t ah[4][4], al[4][4], bh[2][4], bl[2][4];
#pragma unroll
            for (int i = 0; i < 4; i++) {
                uint32_t ro = (uint32_t)((wm * 64 + i * 16 + ar) * GT_STRIDE + ks * 16 + akb) * 2;
                ldsm4(ah[i], st + ro);
                ldsm4(al[i], st + (uint32_t)GT_TILE * 2 + ro);
            }
#pragma unroll
            for (int p = 0; p < 2; p++) {
                uint32_t ro = (uint32_t)((wn * 32 + p * 16 + br) * GT_STRIDE + ks * 16 + bkb) * 2;
                ldsm4(bh[p], st + (uint32_t)GT_TILE * 4 + ro);
                ldsm4(bl[p], st + (uint32_t)GT_TILE * 6 + ro);
            }
            // pass-major: same-accumulator MMAs spaced 16 apart
#pragma unroll
            for (int i = 0; i < 4; i++)
#pragma unroll
                for (int j = 0; j < 4; j++)
                    mma16816(acc[i][j], ah[i], bh[j >> 1][(j & 1) * 2], bh[j >> 1][(j & 1) * 2 + 1]);
#pragma unroll
            for (int i = 0; i < 4; i++)
#pragma unroll
                for (int j = 0; j < 4; j++)
                    mma16816(acc[i][j], ah[i], bl[j >> 1][(j & 1) * 2], bl[j >> 1][(j & 1) * 2 + 1]);
#pragma unroll
            for (int i = 0; i < 4; i++)
#pragma unroll
                for (int j = 0; j < 4; j++)
                    mma16816(acc[i][j], al[i], bh[j >> 1][(j & 1) * 2], bh[j >> 1][(j & 1) * 2 + 1]);
        }
        cp_wait0();
        __syncthreads();
    }

    const int er = lane >> 2;
    const int ec = (lane & 3) * 2;
#pragma unroll
    for (int i = 0; i < 4; i++) {
        int r0 = m0 + wm * 64 + i * 16 + er;
#pragma unroll
        for (int j = 0; j < 4; j++) {
            int cc = n0 + wn * 32 + j * 8 + ec;
            *(float2*)(C + (size_t)r0 * N + cc)       = make_float2(acc[i][j][0], acc[i][j][1]);
            *(float2*)(C + (size_t)(r0 + 8) * N + cc) = make_float2(acc[i][j][2], acc[i][j][3]);
        }
    }
}

// ======================= fp32 -> bf16 hi/lo split (vectorized x4) =======================
__global__ __launch_bounds__(256) void split_bf16(const float* __restrict__ x,
                                                  __nv_bfloat16* __restrict__ hi,
                                                  __nv_bfloat16* __restrict__ lo, int n4) {
    int i = blockIdx.x * blockDim.x + threadIdx.x;
    if (i >= n4) return;
    float4 v = ((const float4*)x)[i];
    __nv_bfloat162 h01 = __floats2bfloat162_rn(v.x, v.y);
    __nv_bfloat162 h23 = __floats2bfloat162_rn(v.z, v.w);
    __nv_bfloat162 l01 = __floats2bfloat162_rn(v.x - __low2float(h01), v.y - __high2float(h01));
    __nv_bfloat162 l23 = __floats2bfloat162_rn(v.z - __low2float(h23), v.w - __high2float(h23));
    ((uint2*)hi)[i] = make_uint2(*(uint32_t*)&h01, *(uint32_t*)&h23);
    ((uint2*)lo)[i] = make_uint2(*(uint32_t*)&l01, *(uint32_t*)&l23);
}

// ======================= prep: RoPE + scale + split + per-head relayout ==================
__global__ __launch_bounds__(256) void prep_kernel(const float* __restrict__ qkv,
                                                   const float* __restrict__ Rs,
                                                   __nv_bfloat16* __restrict__ qh,
                                                   __nv_bfloat16* __restrict__ ql,
                                                   __nv_bfloat16* __restrict__ kh,
                                                   __nv_bfloat16* __restrict__ kl,
                                                   __nv_bfloat16* __restrict__ vh,
                                                   __nv_bfloat16* __restrict__ vl) {
    __shared__ float sR[NTRIP * 9];
    const int t = blockIdx.x;
    const int b = blockIdx.y;
    const int tid = threadIdx.x;

    for (int i = tid; i < NTRIP * 9; i += 256)
        sR[i] = Rs[(size_t)t * NTRIP * 9 + i];
    __syncthreads();

    const float* row = qkv + (size_t)(b * T_SEQ + t) * QKVN;

    for (int task = tid; task < 2 * NH * NTRIP; task += 256) {
        int trip = task & 31;
        int h = (task >> 5) & 15;
        int which = task >> 9;
        const float* src = row + which * (NH * HD) + h * HD + trip * 3;
        const float* R = sR + trip * 9;
        float x0 = src[0], x1 = src[1], x2 = src[2];
        float y0 = R[0] * x0 + R[1] * x1 + R[2] * x2;
        float y1 = R[3] * x0 + R[4] * x1 + R[5] * x2;
        float y2 = R[6] * x0 + R[7] * x1 + R[8] * x2;
        if (which == 0) { y0 *= SCALE_LOG2E; y1 *= SCALE_LOG2E; y2 *= SCALE_LOG2E; }
        size_t dst = ((size_t)(b * NH + h) * T_SEQ + t) * HD + trip * 3;
        __nv_bfloat16* H = which ? kh : qh;
        __nv_bfloat16* L = which ? kl : ql;
        __nv_bfloat16 h0 = __float2bfloat16(y0);
        __nv_bfloat16 h1 = __float2bfloat16(y1);
        __nv_bfloat16 h2 = __float2bfloat16(y2);
        H[dst + 0] = h0; L[dst + 0] = __float2bfloat16(y0 - __bfloat162float(h0));
        H[dst + 1] = h1; L[dst + 1] = __float2bfloat16(y1 - __bfloat162float(h1));
        H[dst + 2] = h2; L[dst + 2] = __float2bfloat16(y2 - __bfloat162float(h2));
    }

    for (int d = tid; d < NH * HD; d += 256) {
        int h = d / HD, dd = d % HD;
        float v = row[2 * NH * HD + d];
        size_t dst = ((size_t)(b * NH + h) * T_SEQ + t) * HD + dd;
        __nv_bfloat16 hv = __float2bfloat16(v);
        vh[dst] = hv;
        vl[dst] = __float2bfloat16(v - __bfloat162float(hv));
    }
}

// ======================= HMMA flash attention v3: Q in regs + K/V double buffer ============
// smem: two KV stages of 4 buffers each (KH|KL|VH|VL), 64x104 bf16 per buffer.
// Q is staged through stage1 at startup, ldsm'd into registers, then stage1 is reused.
#define AT_STR 104
#define KVB (64 * AT_STR * 2)          // 13312 bytes per buffer
#define KV_STAGE_B (4 * KVB)           // 53248 bytes per stage
#define ATT_SMEM (2 * KV_STAGE_B)      // 106496 bytes

__global__ __launch_bounds__(256) void attn_hmma(const __nv_bfloat16* __restrict__ qh,
                                                 const __nv_bfloat16* __restrict__ ql,
                                                 const __nv_bfloat16* __restrict__ kh,
                                                 const __nv_bfloat16* __restrict__ kl,
                                                 const __nv_bfloat16* __restrict__ vh,
                                                 const __nv_bfloat16* __restrict__ vl,
                                                 __nv_bfloat16* __restrict__ ahi,
                                                 __nv_bfloat16* __restrict__ alo) {
    extern __shared__ __align__(128) char smem[];
    const uint32_t sbase = smem_u32(smem);
    const int tid = threadIdx.x;
    const int wid = tid >> 5;
    const int lane = tid & 31;
    const int qt = gridDim.x - 1 - blockIdx.x;
    const int bh = blockIdx.y;
    const int b = bh >> 4;
    const int h = bh & 15;
    const int q0 = qt * 128;

    const size_t bhoff = (size_t)bh * T_SEQ * HD;
    const __nv_bfloat16* qh_b = qh + bhoff;
    const __nv_bfloat16* ql_b = ql + bhoff;
    const __nv_bfloat16* kh_b = kh + bhoff;
    const __nv_bfloat16* kl_b = kl + bhoff;
    const __nv_bfloat16* vh_b = vh + bhoff;
    const __nv_bfloat16* vl_b = vl + bhoff;

    const uint32_t stage0 = sbase;
    const uint32_t stage1 = sbase + KV_STAGE_B;

    // ---- stage Q (hi at stage1+0, lo at stage1+2*KVB; 128x104 each) ----
#pragma unroll
    for (int i = 0; i < 6; i++) {
        int e = tid + i * 256;
        int row = e / 12, c = e % 12;
        uint32_t so = (uint32_t)(row * AT_STR + c * 8) * 2;
        size_t go = (size_t)(q0 + row) * HD + c * 8;
        cp16(stage1 + so, qh_b + go);
        cp16(stage1 + 2 * KVB + so, ql_b + go);
    }
    cp_commit();   // group: Q

    // ---- KV tile kt=0 -> stage0 ----
#pragma unroll
    for (int i = 0; i < 3; i++) {
        int e = tid + i * 256;
        int row = e / 12, c = e % 12;
        uint32_t so = (uint32_t)(row * AT_STR + c * 8) * 2;
        size_t go = (size_t)row * HD + c * 8;
        cp16(stage0 + 0 * KVB + so, kh_b + go);
        cp16(stage0 + 1 * KVB + so, kl_b + go);
        cp16(stage0 + 2 * KVB + so, vh_b + go);
        cp16(stage0 + 3 * KVB + so, vl_b + go);
    }
    cp_commit();   // group: KV0

    const int ar  = lane & 15;
    const int akb = (lane >> 4) << 3;
    const int br  = (lane & 7) + ((lane >> 4) << 3);
    const int bkb = ((lane >> 3) & 1) << 3;
    const int vr  = (lane & 7) + (((lane >> 3) & 1) << 3);
    const int vcb = ((lane >> 4) & 1) << 3;

    // ---- Q fragments into registers (freed from smem afterwards) ----
    cp_wait1();         // Q group done (KV0 may still be in flight)
    __syncthreads();    // Q writes visible to all warps
    uint32_t qa_h[6][4], qa_l[6][4];
#pragma unroll
    for (int t = 0; t < 6; t++) {
        uint32_t qo = (uint32_t)((wid * 16 + ar) * AT_STR + t * 16 + akb) * 2;
        ldsm4(qa_h[t], stage1 + qo);
        ldsm4(qa_l[t], stage1 + 2 * KVB + qo);
    }

    float oacc[12][4];
#pragma unroll
    for (int j = 0; j < 12; j++)
#pragma unroll
        for (int q = 0; q < 4; q++) oacc[j][q] = 0.0f;
    float m0r = -1e30f, m1r = -1e30f, l0r = 0.0f, l1r = 0.0f;

    const int ktiles = 2 * (qt + 1);
    const int r0loc = lane >> 2;
    const int qrow0 = q0 + wid * 16 + r0loc;
    const int qrow1 = qrow0 + 8;

    for (int kt = 0; kt < ktiles; kt++) {
        cp_wait0();         // KV(kt) landed
        __syncthreads();    // visible to all; all warps done reading the other stage (and Q)
        if (kt + 1 < ktiles) {
            uint32_t stn = ((kt + 1) & 1) ? stage1 : stage0;
#pragma unroll
            for (int i = 0; i < 3; i++) {
                int e = tid + i * 256;
                int row = e / 12, c = e % 12;
                uint32_t so = (uint32_t)(row * AT_STR + c * 8) * 2;
                size_t go = (size_t)((kt + 1) * 64 + row) * HD + c * 8;
                cp16(stn + 0 * KVB + so, kh_b + go);
                cp16(stn + 1 * KVB + so, kl_b + go);
                cp16(stn + 2 * KVB + so, vh_b + go);
                cp16(stn + 3 * KVB + so, vl_b + go);
            }
            cp_commit();
        }
        const uint32_t st = (kt & 1) ? stage1 : stage0;

        // ---- S = Q K^T (3-pass compensated) ----
        float sacc[8][4];
#pragma unroll
        for (int j = 0; j < 8; j++)
#pragma unroll
            for (int q = 0; q < 4; q++) sacc[j][q] = 0.0f;

#pragma unroll
        for (int t = 0; t < 6; t++) {
#pragma unroll
            for (int g = 0; g < 4; g++) {
                uint32_t kb_h[4], kb_l[4];
                uint32_t ko = (uint32_t)((g * 16 + br) * AT_STR + t * 16 + bkb) * 2;
                ldsm4(kb_h, st + 0 * KVB + ko);
                ldsm4(kb_l, st + 1 * KVB + ko);
#pragma unroll
                for (int j2 = 0; j2 < 2; j2++) {
                    int j = g * 2 + j2;
                    mma16816(sacc[j], qa_h[t], kb_h[j2 * 2], kb_h[j2 * 2 + 1]);
                    mma16816(sacc[j], qa_h[t], kb_l[j2 * 2], kb_l[j2 * 2 + 1]);
                    mma16816(sacc[j], qa_l[t], kb_h[j2 * 2], kb_h[j2 * 2 + 1]);
                }
            }
        }

        // ---- causal mask ----
        if (kt >= ktiles - 2) {
            int kbase = kt * 64 + (lane & 3) * 2;
#pragma unroll
            for (int j = 0; j < 8; j++) {
                int k0i = kbase + j * 8;
                if (k0i > qrow0)     sacc[j][0] = -1e30f;
                if (k0i + 1 > qrow0) sacc[j][1] = -1e30f;
                if (k0i > qrow1)     sacc[j][2] = -1e30f;
                if (k0i + 1 > qrow1) sacc[j][3] = -1e30f;
            }
        }

        // ---- online softmax (log2 domain) ----
        float mx0 = -1e30f, mx1 = -1e30f;
#pragma unroll
        for (int j = 0; j < 8; j++) {
            mx0 = fmaxf(mx0, fmaxf(sacc[j][0], sacc[j][1]));
            mx1 = fmaxf(mx1, fmaxf(sacc[j][2], sacc[j][3]));
        }
        mx0 = fmaxf(mx0, __shfl_xor_sync(0xffffffffu, mx0, 1));
        mx0 = fmaxf(mx0, __shfl_xor_sync(0xffffffffu, mx0, 2));
        mx1 = fmaxf(mx1, __shfl_xor_sync(0xffffffffu, mx1, 1));
        mx1 = fmaxf(mx1, __shfl_xor_sync(0xffffffffu, mx1, 2));
        float mn0 = fmaxf(m0r, mx0), mn1 = fmaxf(m1r, mx1);
        float corr0 = ex2f(m0r - mn0), corr1 = ex2f(m1r - mn1);
        m0r = mn0; m1r = mn1;

        uint32_t pa_h[8][2], pa_l[8][2];
        float rs0 = 0.0f, rs1 = 0.0f;
#pragma unroll
        for (int j = 0; j < 8; j++) {
            float p0 = ex2f(sacc[j][0] - mn0);
            float p1 = ex2f(sacc[j][1] - mn0);
            float p2 = ex2f(sacc[j][2] - mn1);
            float p3 = ex2f(sacc[j][3] - mn1);
            rs0 += p0 + p1; rs1 += p2 + p3;
            __nv_bfloat162 h01 = __floats2bfloat162_rn(p0, p1);
            __nv_bfloat162 h23 = __floats2bfloat162_rn(p2, p3);
            pa_h[j][0] = *(uint32_t*)&h01;
            pa_h[j][1] = *(uint32_t*)&h23;
            __nv_bfloat162 l01 = __floats2bfloat162_rn(p0 - __low2float(h01), p1 - __high2float(h01));
            __nv_bfloat162 l23 = __floats2bfloat162_rn(p2 - __low2float(h23), p3 - __high2float(h23));
            pa_l[j][0] = *(uint32_t*)&l01;
            pa_l[j][1] = *(uint32_t*)&l23;
        }
        rs0 += __shfl_xor_sync(0xffffffffu, rs0, 1);
        rs0 += __shfl_xor_sync(0xffffffffu, rs0, 2);
        rs1 += __shfl_xor_sync(0xffffffffu, rs1, 1);
        rs1 += __shfl_xor_sync(0xffffffffu, rs1, 2);
        l0r = l0r * corr0 + rs0;
        l1r = l1r * corr1 + rs1;
#pragma unroll
        for (int j = 0; j < 12; j++) {
            oacc[j][0] *= corr0; oacc[j][1] *= corr0;
            oacc[j][2] *= corr1; oacc[j][3] *= corr1;
        }

        // ---- O += P V (3-pass compensated) ----
#pragma unroll
        for (int kc = 0; kc < 4; kc++) {
            uint32_t a_h[4] = {pa_h[2 * kc][0], pa_h[2 * kc][1], pa_h[2 * kc + 1][0], pa_h[2 * kc + 1][1]};
            uint32_t a_l[4] = {pa_l[2 * kc][0], pa_l[2 * kc][1], pa_l[2 * kc + 1][0], pa_l[2 * kc + 1][1]};
            uint32_t vrow = (uint32_t)(kc * 16 + vr);
#pragma unroll
            for (int g = 0; g < 6; g++) {
                uint32_t vb_h[4], vb_l[4];
                uint32_t vo = (vrow * AT_STR + g * 16 + vcb) * 2;
                ldsm4t(vb_h, st + 2 * KVB + vo);
                ldsm4t(vb_l, st + 3 * KVB + vo);
#pragma unroll
                for (int j2 = 0; j2 < 2; j2++) {
                    int jt = g * 2 + j2;
                    mma16816(oacc[jt], a_h, vb_h[j2 * 2], vb_h[j2 * 2 + 1]);
                    mma16816(oacc[jt], a_h, vb_l[j2 * 2], vb_l[j2 * 2 + 1]);
                    mma16816(oacc[jt], a_l, vb_h[j2 * 2], vb_h[j2 * 2 + 1]);
                }
            }
        }
    }

    // ---- epilogue ----
    float inv0 = 1.0f / l0r, inv1 = 1.0f / l1r;
    size_t base0 = (size_t)(b * T_SEQ + qrow0) * DM + h * HD;
    size_t base1 = (size_t)(b * T_SEQ + qrow1) * DM + h * HD;
#pragma unroll
    for (int j = 0; j < 12; j++) {
        int col = j * 8 + (lane & 3) * 2;
        float v0 = oacc[j][0] * inv0, v1 = oacc[j][1] * inv0;
        float v2 = oacc[j][2] * inv1, v3 = oacc[j][3] * inv1;
        __nv_bfloat162 h01 = __floats2bfloat162_rn(v0, v1);
        __nv_bfloat162 h23 = __floats2bfloat162_rn(v2, v3);
        *(__nv_bfloat162*)(ahi + base0 + col) = h01;
        *(__nv_bfloat162*)(ahi + base1 + col) = h23;
        __nv_bfloat162 l01 = __floats2bfloat162_rn(v0 - __low2float(h01), v1 - __high2float(h01));
        __nv_bfloat162 l23 = __floats2bfloat162_rn(v2 - __low2float(h23), v3 - __high2float(h23));
        *(__nv_bfloat162*)(alo + base0 + col) = l01;
        *(__nv_bfloat162*)(alo + base1 + col) = l23;
    }
}

// ======================= launch =======================
extern "C" void kernel_launch(void* const* d_in, const int* in_sizes, int n_in,
                              void* d_out, int out_size) {
    const float* x     = (const float*)d_in[0];
    const float* w_qkv = (const float*)d_in[1];
    const float* w_o   = (const float*)d_in[2];
    const float* Rs    = (const float*)d_in[3];
    float* out = (float*)d_out;

    float* qkv;
    cudaGetSymbolAddress((void**)&qkv, g_qkv);
    __nv_bfloat16 *xhi, *xlo, *wqh, *wql, *woh, *wol, *ahi, *alo;
    cudaGetSymbolAddress((void**)&xhi, g_xhi);
    cudaGetSymbolAddress((void**)&xlo, g_xlo);
    cudaGetSymbolAddress((void**)&wqh, g_wqh);
    cudaGetSymbolAddress((void**)&wql, g_wql);
    cudaGetSymbolAddress((void**)&woh, g_woh);
    cudaGetSymbolAddress((void**)&wol, g_wol);
    cudaGetSymbolAddress((void**)&ahi, g_ahi);
    cudaGetSymbolAddress((void**)&alo, g_alo);
    __nv_bfloat16 *qh, *ql, *kh, *kl, *vh, *vl;
    cudaGetSymbolAddress((void**)&qh, g_qh);
    cudaGetSymbolAddress((void**)&ql, g_ql);
    cudaGetSymbolAddress((void**)&kh, g_kh);
    cudaGetSymbolAddress((void**)&kl, g_kl);
    cudaGetSymbolAddress((void**)&vh, g_vh);
    cudaGetSymbolAddress((void**)&vl, g_vl);

    // 0) bf16 hi/lo splits (vectorized x4)
    {
        int n1 = MROWS * DM / 4, n2 = QKVN * DM / 4, n3 = DM * DM / 4;
        split_bf16<<<(n1 + 255) / 256, 256>>>(x, xhi, xlo, n1);
        split_bf16<<<(n2 + 255) / 256, 256>>>(w_qkv, wqh, wql, n2);
        split_bf16<<<(n3 + 255) / 256, 256>>>(w_o, woh, wol, n3);
    }

    // 1) QKV projection
    cudaFuncSetAttribute(gemm_hmma3, cudaFuncAttributeMaxDynamicSharedMemorySize, GEMM_SMEM);
    gemm_hmma3<<<dim3(QKVN / 128, MROWS / 128), 256, GEMM_SMEM>>>(
        xhi, xlo, wqh, wql, qkv, MROWS, QKVN, DM);

    // 2) RoPE + scale + split + per-head relayout
    prep_kernel<<<dim3(T_SEQ, BATCH), 256>>>(qkv, Rs, qh, ql, kh, kl, vh, vl);

    // 3) HMMA flash attention -> ahi/alo
    cudaFuncSetAttribute(attn_hmma, cudaFuncAttributeMaxDynamicSharedMemorySize, ATT_SMEM);
    attn_hmma<<<dim3(T_SEQ / 128, BATCH * NH), 256, ATT_SMEM>>>(
        qh, ql, kh, kl, vh, vl, ahi, alo);

    // 4) Out-projection
    gemm_hmma3<<<dim3(DM / 128, MROWS / 128), 256, GEMM_SMEM>>>(
        ahi, alo, woh, wol, out, MROWS, DM, DM);
}

// round 12
// speedup vs baseline: 1.3056x; 1.1213x over previous
#include <cuda_runtime.h>
#include <cuda_bf16.h>
#include <cstdint>
#include <math.h>

// Problem constants (fixed shapes)
#define T_SEQ 2048
#define BATCH 2
#define DM    1536
#define NH    16
#define HD    96
#define QKVN  4608          // 3 * NH * HD
#define MROWS 4096          // BATCH * T_SEQ
#define NTRIP 32            // HD / 3

// scale * log2(e): fold softmax scale + exp->exp2 conversion into q
#define SCALE_LOG2E 0.14724463267f

// Scratch (device globals: no allocations allowed)
__device__ __align__(128) float g_qkv[(size_t)MROWS * QKVN];

__device__ __align__(128) __nv_bfloat16 g_xhi[(size_t)MROWS * DM];
__device__ __align__(128) __nv_bfloat16 g_xlo[(size_t)MROWS * DM];
__device__ __align__(128) __nv_bfloat16 g_wqh[(size_t)QKVN * DM];
__device__ __align__(128) __nv_bfloat16 g_wql[(size_t)QKVN * DM];
__device__ __align__(128) __nv_bfloat16 g_woh[(size_t)DM * DM];
__device__ __align__(128) __nv_bfloat16 g_wol[(size_t)DM * DM];
__device__ __align__(128) __nv_bfloat16 g_ahi[(size_t)MROWS * DM];
__device__ __align__(128) __nv_bfloat16 g_alo[(size_t)MROWS * DM];

#define BHSZ ((size_t)BATCH * NH * T_SEQ * HD)
__device__ __align__(128) __nv_bfloat16 g_qh[BHSZ];
__device__ __align__(128) __nv_bfloat16 g_ql[BHSZ];
__device__ __align__(128) __nv_bfloat16 g_kh[BHSZ];
__device__ __align__(128) __nv_bfloat16 g_kl[BHSZ];
__device__ __align__(128) __nv_bfloat16 g_vh[BHSZ];
__device__ __align__(128) __nv_bfloat16 g_vl[BHSZ];

// ======================= helpers (base ISA only) =======================
__device__ __forceinline__ uint32_t smem_u32(const void* p) {
    uint32_t a;
    asm("{ .reg .u64 t; cvta.to.shared.u64 t, %1; cvt.u32.u64 %0, t; }" : "=r"(a) : "l"(p));
    return a;
}

__device__ __forceinline__ void cp16(uint32_t saddr, const void* gptr) {
    asm volatile("cp.async.cg.shared.global [%0], [%1], 16;" :: "r"(saddr), "l"(gptr));
}
__device__ __forceinline__ void cp_commit() { asm volatile("cp.async.commit_group;"); }
__device__ __forceinline__ void cp_wait0()  { asm volatile("cp.async.wait_group 0;" ::: "memory"); }
__device__ __forceinline__ void cp_wait1()  { asm volatile("cp.async.wait_group 1;" ::: "memory"); }

__device__ __forceinline__ void ldsm4(uint32_t* r, uint32_t addr) {
    asm volatile("ldmatrix.sync.aligned.m8n8.x4.shared.b16 {%0,%1,%2,%3}, [%4];"
                 : "=r"(r[0]), "=r"(r[1]), "=r"(r[2]), "=r"(r[3]) : "r"(addr));
}
__device__ __forceinline__ void ldsm4t(uint32_t* r, uint32_t addr) {
    asm volatile("ldmatrix.sync.aligned.m8n8.x4.trans.shared.b16 {%0,%1,%2,%3}, [%4];"
                 : "=r"(r[0]), "=r"(r[1]), "=r"(r[2]), "=r"(r[3]) : "r"(addr));
}

__device__ __forceinline__ void mma16816(float* c, const uint32_t* a, uint32_t b0, uint32_t b1) {
    asm volatile(
        "mma.sync.aligned.m16n8k16.row.col.f32.bf16.bf16.f32 "
        "{%0,%1,%2,%3}, {%4,%5,%6,%7}, {%8,%9}, {%0,%1,%2,%3};"
        : "+f"(c[0]), "+f"(c[1]), "+f"(c[2]), "+f"(c[3])
        : "r"(a[0]), "r"(a[1]), "r"(a[2]), "r"(a[3]), "r"(b0), "r"(b1));
}

__device__ __forceinline__ float ex2f(float x) {
    float y;
    asm("ex2.approx.f32 %0, %1;" : "=f"(y) : "f"(x));
    return y;
}

// ======================= bf16x3 HMMA GEMM v3: 128x256 block, 64x64 warp tiles ==============
// 8 warps: wm = wid&1 (two 64-row slabs), wn = wid>>1 (four 64-col slabs).
// smem/stage: AH(10240) | AL(10240) | BH(20480) | BL(20480) = 61440 B; 2 stages = 120 KB.
#define GT_STRIDE 40                           // 80B rows: 16B-aligned, conflict-free
#define GV_AH 0
#define GV_AL 10240
#define GV_BH 20480
#define GV_BL 40960
#define GV_STAGE_B 61440
#define GEMM_SMEM (2 * GV_STAGE_B)             // 122880 bytes, 1 CTA/SM

__device__ __forceinline__ void issue_chunk(uint32_t sbase, int stage,
                                            const __nv_bfloat16* Ahi, const __nv_bfloat16* Alo,
                                            const __nv_bfloat16* Bhi, const __nv_bfloat16* Blo,
                                            int K, int m0, int n0, int col0, int tid) {
    uint32_t st = sbase + (uint32_t)stage * GV_STAGE_B;
    // A: 128 rows x 4 chunks of 16B (hi + lo)
#pragma unroll
    for (int i = 0; i < 2; i++) {
        int e = tid + i * 256;       // 0..511
        int row = e >> 2, q = e & 3;
        uint32_t so = (uint32_t)(row * GT_STRIDE + q * 8) * 2;
        size_t go = (size_t)(m0 + row) * K + col0 + q * 8;
        cp16(st + GV_AH + so, Ahi + go);
        cp16(st + GV_AL + so, Alo + go);
    }
    // B: 256 rows x 4 chunks of 16B (hi + lo)
#pragma unroll
    for (int i = 0; i < 4; i++) {
        int e = tid + i * 256;       // 0..1023
        int row = e >> 2, q = e & 3;
        uint32_t so = (uint32_t)(row * GT_STRIDE + q * 8) * 2;
        size_t go = (size_t)(n0 + row) * K + col0 + q * 8;
        cp16(st + GV_BH + so, Bhi + go);
        cp16(st + GV_BL + so, Blo + go);
    }
}

__global__ __launch_bounds__(256, 1) void gemm_hmma3(const __nv_bfloat16* __restrict__ Ahi,
                                                     const __nv_bfloat16* __restrict__ Alo,
                                                     const __nv_bfloat16* __restrict__ Bhi,
                                                     const __nv_bfloat16* __restrict__ Blo,
                                                     float* __restrict__ C,
                                                     int M, int N, int K) {
    extern __shared__ __align__(128) char smem[];
    const uint32_t sbase = smem_u32(smem);
    const int tid = threadIdx.x;
    const int wid = tid >> 5;
    const int lane = tid & 31;
    const int wm = wid & 1;        // 0..1 -> 64-row slab
    const int wn = wid >> 1;       // 0..3 -> 64-col slab
    const int m0 = blockIdx.y * 128;
    const int n0 = blockIdx.x * 256;
    const int nchunk = K / 32;

    float acc[4][8][4];
#pragma unroll
    for (int i = 0; i < 4; i++)
#pragma unroll
        for (int j = 0; j < 8; j++)
#pragma unroll
            for (int q = 0; q < 4; q++) acc[i][j][q] = 0.0f;

    const int ar  = lane & 15;
    const int akb = (lane >> 4) << 3;
    const int br  = (lane & 7) + ((lane >> 4) << 3);
    const int bkb = ((lane >> 3) & 1) << 3;

    issue_chunk(sbase, 0, Ahi, Alo, Bhi, Blo, K, m0, n0, 0, tid);
    cp_commit();
    cp_wait0();
    __syncthreads();

    for (int c = 0; c < nchunk; c++) {
        if (c + 1 < nchunk) {
            issue_chunk(sbase, (c + 1) & 1, Ahi, Alo, Bhi, Blo, K, m0, n0, (c + 1) * 32, tid);
            cp_commit();
        }
        const uint32_t st = sbase + (uint32_t)(c & 1) * GV_STAGE_B;
#pragma unroll
        for (int ks = 0; ks < 2; ks++) {
            uint32_t ah[4][4], al[4][4], bh[4][4], bl[4][4];
#pragma unroll
            for (int i = 0; i < 4; i++) {
                uint32_t ro = (uint32_t)((wm * 64 + i * 16 + ar) * GT_STRIDE + ks * 16 + akb) * 2;
                ldsm4(ah[i], st + GV_AH + ro);
                ldsm4(al[i], st + GV_AL + ro);
            }
#pragma unroll
            for (int p = 0; p < 4; p++) {
                uint32_t ro = (uint32_t)((wn * 64 + p * 16 + br) * GT_STRIDE + ks * 16 + bkb) * 2;
                ldsm4(bh[p], st + GV_BH + ro);
                ldsm4(bl[p], st + GV_BL + ro);
            }
            // pass-major: same-accumulator MMAs spaced 32 apart
#pragma unroll
            for (int i = 0; i < 4; i++)
#pragma unroll
                for (int j = 0; j < 8; j++)
                    mma16816(acc[i][j], ah[i], bh[j >> 1][(j & 1) * 2], bh[j >> 1][(j & 1) * 2 + 1]);
#pragma unroll
            for (int i = 0; i < 4; i++)
#pragma unroll
                for (int j = 0; j < 8; j++)
                    mma16816(acc[i][j], ah[i], bl[j >> 1][(j & 1) * 2], bl[j >> 1][(j & 1) * 2 + 1]);
#pragma unroll
            for (int i = 0; i < 4; i++)
#pragma unroll
                for (int j = 0; j < 8; j++)
                    mma16816(acc[i][j], al[i], bh[j >> 1][(j & 1) * 2], bh[j >> 1][(j & 1) * 2 + 1]);
        }
        cp_wait0();
        __syncthreads();
    }

    const int er = lane >> 2;
    const int ec = (lane & 3) * 2;
#pragma unroll
    for (int i = 0; i < 4; i++) {
        int r0 = m0 + wm * 64 + i * 16 + er;
#pragma unroll
        for (int j = 0; j < 8; j++) {
            int cc = n0 + wn * 64 + j * 8 + ec;
            *(float2*)(C + (size_t)r0 * N + cc)       = make_float2(acc[i][j][0], acc[i][j][1]);
            *(float2*)(C + (size_t)(r0 + 8) * N + cc) = make_float2(acc[i][j][2], acc[i][j][3]);
        }
    }
}

// ======================= fp32 -> bf16 hi/lo split (vectorized x4) =======================
__global__ __launch_bounds__(256) void split_bf16(const float* __restrict__ x,
                                                  __nv_bfloat16* __restrict__ hi,
                                                  __nv_bfloat16* __restrict__ lo, int n4) {
    int i = blockIdx.x * blockDim.x + threadIdx.x;
    if (i >= n4) return;
    float4 v = ((const float4*)x)[i];
    __nv_bfloat162 h01 = __floats2bfloat162_rn(v.x, v.y);
    __nv_bfloat162 h23 = __floats2bfloat162_rn(v.z, v.w);
    __nv_bfloat162 l01 = __floats2bfloat162_rn(v.x - __low2float(h01), v.y - __high2float(h01));
    __nv_bfloat162 l23 = __floats2bfloat162_rn(v.z - __low2float(h23), v.w - __high2float(h23));
    ((uint2*)hi)[i] = make_uint2(*(uint32_t*)&h01, *(uint32_t*)&h23);
    ((uint2*)lo)[i] = make_uint2(*(uint32_t*)&l01, *(uint32_t*)&l23);
}

// ======================= prep: RoPE + scale + split + per-head relayout ==================
__global__ __launch_bounds__(256) void prep_kernel(const float* __restrict__ qkv,
                                                   const float* __restrict__ Rs,
                                                   __nv_bfloat16* __restrict__ qh,
                                                   __nv_bfloat16* __restrict__ ql,
                                                   __nv_bfloat16* __restrict__ kh,
                                                   __nv_bfloat16* __restrict__ kl,
                                                   __nv_bfloat16* __restrict__ vh,
                                                   __nv_bfloat16* __restrict__ vl) {
    __shared__ float sR[NTRIP * 9];
    const int t = blockIdx.x;
    const int b = blockIdx.y;
    const int tid = threadIdx.x;

    for (int i = tid; i < NTRIP * 9; i += 256)
        sR[i] = Rs[(size_t)t * NTRIP * 9 + i];
    __syncthreads();

    const float* row = qkv + (size_t)(b * T_SEQ + t) * QKVN;

    for (int task = tid; task < 2 * NH * NTRIP; task += 256) {
        int trip = task & 31;
        int h = (task >> 5) & 15;
        int which = task >> 9;
        const float* src = row + which * (NH * HD) + h * HD + trip * 3;
        const float* R = sR + trip * 9;
        float x0 = src[0], x1 = src[1], x2 = src[2];
        float y0 = R[0] * x0 + R[1] * x1 + R[2] * x2;
        float y1 = R[3] * x0 + R[4] * x1 + R[5] * x2;
        float y2 = R[6] * x0 + R[7] * x1 + R[8] * x2;
        if (which == 0) { y0 *= SCALE_LOG2E; y1 *= SCALE_LOG2E; y2 *= SCALE_LOG2E; }
        size_t dst = ((size_t)(b * NH + h) * T_SEQ + t) * HD + trip * 3;
        __nv_bfloat16* H = which ? kh : qh;
        __nv_bfloat16* L = which ? kl : ql;
        __nv_bfloat16 h0 = __float2bfloat16(y0);
        __nv_bfloat16 h1 = __float2bfloat16(y1);
        __nv_bfloat16 h2 = __float2bfloat16(y2);
        H[dst + 0] = h0; L[dst + 0] = __float2bfloat16(y0 - __bfloat162float(h0));
        H[dst + 1] = h1; L[dst + 1] = __float2bfloat16(y1 - __bfloat162float(h1));
        H[dst + 2] = h2; L[dst + 2] = __float2bfloat16(y2 - __bfloat162float(h2));
    }

    for (int d = tid; d < NH * HD; d += 256) {
        int h = d / HD, dd = d % HD;
        float v = row[2 * NH * HD + d];
        size_t dst = ((size_t)(b * NH + h) * T_SEQ + t) * HD + dd;
        __nv_bfloat16 hv = __float2bfloat16(v);
        vh[dst] = hv;
        vl[dst] = __float2bfloat16(v - __bfloat162float(hv));
    }
}

// ======================= HMMA flash attention v3 (unchanged from R11) ======================
#define AT_STR 104
#define KVB (64 * AT_STR * 2)
#define KV_STAGE_B (4 * KVB)
#define ATT_SMEM (2 * KV_STAGE_B)

__global__ __launch_bounds__(256) void attn_hmma(const __nv_bfloat16* __restrict__ qh,
                                                 const __nv_bfloat16* __restrict__ ql,
                                                 const __nv_bfloat16* __restrict__ kh,
                                                 const __nv_bfloat16* __restrict__ kl,
                                                 const __nv_bfloat16* __restrict__ vh,
                                                 const __nv_bfloat16* __restrict__ vl,
                                                 __nv_bfloat16* __restrict__ ahi,
                                                 __nv_bfloat16* __restrict__ alo) {
    extern __shared__ __align__(128) char smem[];
    const uint32_t sbase = smem_u32(smem);
    const int tid = threadIdx.x;
    const int wid = tid >> 5;
    const int lane = tid & 31;
    const int qt = gridDim.x - 1 - blockIdx.x;
    const int bh = blockIdx.y;
    const int b = bh >> 4;
    const int h = bh & 15;
    const int q0 = qt * 128;

    const size_t bhoff = (size_t)bh * T_SEQ * HD;
    const __nv_bfloat16* qh_b = qh + bhoff;
    const __nv_bfloat16* ql_b = ql + bhoff;
    const __nv_bfloat16* kh_b = kh + bhoff;
    const __nv_bfloat16* kl_b = kl + bhoff;
    const __nv_bfloat16* vh_b = vh + bhoff;
    const __nv_bfloat16* vl_b = vl + bhoff;

    const uint32_t stage0 = sbase;
    const uint32_t stage1 = sbase + KV_STAGE_B;

#pragma unroll
    for (int i = 0; i < 6; i++) {
        int e = tid + i * 256;
        int row = e / 12, c = e % 12;
        uint32_t so = (uint32_t)(row * AT_STR + c * 8) * 2;
        size_t go = (size_t)(q0 + row) * HD + c * 8;
        cp16(stage1 + so, qh_b + go);
        cp16(stage1 + 2 * KVB + so, ql_b + go);
    }
    cp_commit();   // group: Q

#pragma unroll
    for (int i = 0; i < 3; i++) {
        int e = tid + i * 256;
        int row = e / 12, c = e % 12;
        uint32_t so = (uint32_t)(row * AT_STR + c * 8) * 2;
        size_t go = (size_t)row * HD + c * 8;
        cp16(stage0 + 0 * KVB + so, kh_b + go);
        cp16(stage0 + 1 * KVB + so, kl_b + go);
        cp16(stage0 + 2 * KVB + so, vh_b + go);
        cp16(stage0 + 3 * KVB + so, vl_b + go);
    }
    cp_commit();   // group: KV0

    const int ar  = lane & 15;
    const int akb = (lane >> 4) << 3;
    const int br  = (lane & 7) + ((lane >> 4) << 3);
    const int bkb = ((lane >> 3) & 1) << 3;
    const int vr  = (lane & 7) + (((lane >> 3) & 1) << 3);
    const int vcb = ((lane >> 4) & 1) << 3;

    cp_wait1();
    __syncthreads();
    uint32_t qa_h[6][4], qa_l[6][4];
#pragma unroll
    for (int t = 0; t < 6; t++) {
        uint32_t qo = (uint32_t)((wid * 16 + ar) * AT_STR + t * 16 + akb) * 2;
        ldsm4(qa_h[t], stage1 + qo);
        ldsm4(qa_l[t], stage1 + 2 * KVB + qo);
    }

    float oacc[12][4];
#pragma unroll
    for (int j = 0; j < 12; j++)
#pragma unroll
        for (int q = 0; q < 4; q++) oacc[j][q] = 0.0f;
    float m0r = -1e30f, m1r = -1e30f, l0r = 0.0f, l1r = 0.0f;

    const int ktiles = 2 * (qt + 1);
    const int r0loc = lane >> 2;
    const int qrow0 = q0 + wid * 16 + r0loc;
    const int qrow1 = qrow0 + 8;

    for (int kt = 0; kt < ktiles; kt++) {
        cp_wait0();
        __syncthreads();
        if (kt + 1 < ktiles) {
            uint32_t stn = ((kt + 1) & 1) ? stage1 : stage0;
#pragma unroll
            for (int i = 0; i < 3; i++) {
                int e = tid + i * 256;
                int row = e / 12, c = e % 12;
                uint32_t so = (uint32_t)(row * AT_STR + c * 8) * 2;
                size_t go = (size_t)((kt + 1) * 64 + row) * HD + c * 8;
                cp16(stn + 0 * KVB + so, kh_b + go);
                cp16(stn + 1 * KVB + so, kl_b + go);
                cp16(stn + 2 * KVB + so, vh_b + go);
                cp16(stn + 3 * KVB + so, vl_b + go);
            }
            cp_commit();
        }
        const uint32_t st = (kt & 1) ? stage1 : stage0;

        float sacc[8][4];
#pragma unroll
        for (int j = 0; j < 8; j++)
#pragma unroll
            for (int q = 0; q < 4; q++) sacc[j][q] = 0.0f;

#pragma unroll
        for (int t = 0; t < 6; t++) {
#pragma unroll
            for (int g = 0; g < 4; g++) {
                uint32_t kb_h[4], kb_l[4];
                uint32_t ko = (uint32_t)((g * 16 + br) * AT_STR + t * 16 + bkb) * 2;
                ldsm4(kb_h, st + 0 * KVB + ko);
                ldsm4(kb_l, st + 1 * KVB + ko);
#pragma unroll
                for (int j2 = 0; j2 < 2; j2++) {
                    int j = g * 2 + j2;
                    mma16816(sacc[j], qa_h[t], kb_h[j2 * 2], kb_h[j2 * 2 + 1]);
                    mma16816(sacc[j], qa_h[t], kb_l[j2 * 2], kb_l[j2 * 2 + 1]);
                    mma16816(sacc[j], qa_l[t], kb_h[j2 * 2], kb_h[j2 * 2 + 1]);
                }
            }
        }

        if (kt >= ktiles - 2) {
            int kbase = kt * 64 + (lane & 3) * 2;
#pragma unroll
            for (int j = 0; j < 8; j++) {
                int k0i = kbase + j * 8;
                if (k0i > qrow0)     sacc[j][0] = -1e30f;
                if (k0i + 1 > qrow0) sacc[j][1] = -1e30f;
                if (k0i > qrow1)     sacc[j][2] = -1e30f;
                if (k0i + 1 > qrow1) sacc[j][3] = -1e30f;
            }
        }

        float mx0 = -1e30f, mx1 = -1e30f;
#pragma unroll
        for (int j = 0; j < 8; j++) {
            mx0 = fmaxf(mx0, fmaxf(sacc[j][0], sacc[j][1]));
            mx1 = fmaxf(mx1, fmaxf(sacc[j][2], sacc[j][3]));
        }
        mx0 = fmaxf(mx0, __shfl_xor_sync(0xffffffffu, mx0, 1));
        mx0 = fmaxf(mx0, __shfl_xor_sync(0xffffffffu, mx0, 2));
        mx1 = fmaxf(mx1, __shfl_xor_sync(0xffffffffu, mx1, 1));
        mx1 = fmaxf(mx1, __shfl_xor_sync(0xffffffffu, mx1, 2));
        float mn0 = fmaxf(m0r, mx0), mn1 = fmaxf(m1r, mx1);
        float corr0 = ex2f(m0r - mn0), corr1 = ex2f(m1r - mn1);
        m0r = mn0; m1r = mn1;

        uint32_t pa_h[8][2], pa_l[8][2];
        float rs0 = 0.0f, rs1 = 0.0f;
#pragma unroll
        for (int j = 0; j < 8; j++) {
            float p0 = ex2f(sacc[j][0] - mn0);
            float p1 = ex2f(sacc[j][1] - mn0);
            float p2 = ex2f(sacc[j][2] - mn1);
            float p3 = ex2f(sacc[j][3] - mn1);
            rs0 += p0 + p1; rs1 += p2 + p3;
            __nv_bfloat162 h01 = __floats2bfloat162_rn(p0, p1);
            __nv_bfloat162 h23 = __floats2bfloat162_rn(p2, p3);
            pa_h[j][0] = *(uint32_t*)&h01;
            pa_h[j][1] = *(uint32_t*)&h23;
            __nv_bfloat162 l01 = __floats2bfloat162_rn(p0 - __low2float(h01), p1 - __high2float(h01));
            __nv_bfloat162 l23 = __floats2bfloat162_rn(p2 - __low2float(h23), p3 - __high2float(h23));
            pa_l[j][0] = *(uint32_t*)&l01;
            pa_l[j][1] = *(uint32_t*)&l23;
        }
        rs0 += __shfl_xor_sync(0xffffffffu, rs0, 1);
        rs0 += __shfl_xor_sync(0xffffffffu, rs0, 2);
        rs1 += __shfl_xor_sync(0xffffffffu, rs1, 1);
        rs1 += __shfl_xor_sync(0xffffffffu, rs1, 2);
        l0r = l0r * corr0 + rs0;
        l1r = l1r * corr1 + rs1;
#pragma unroll
        for (int j = 0; j < 12; j++) {
            oacc[j][0] *= corr0; oacc[j][1] *= corr0;
            oacc[j][2] *= corr1; oacc[j][3] *= corr1;
        }

#pragma unroll
        for (int kc = 0; kc < 4; kc++) {
            uint32_t a_h[4] = {pa_h[2 * kc][0], pa_h[2 * kc][1], pa_h[2 * kc + 1][0], pa_h[2 * kc + 1][1]};
            uint32_t a_l[4] = {pa_l[2 * kc][0], pa_l[2 * kc][1], pa_l[2 * kc + 1][0], pa_l[2 * kc + 1][1]};
            uint32_t vrow = (uint32_t)(kc * 16 + vr);
#pragma unroll
            for (int g = 0; g < 6; g++) {
                uint32_t vb_h[4], vb_l[4];
                uint32_t vo = (vrow * AT_STR + g * 16 + vcb) * 2;
                ldsm4t(vb_h, st + 2 * KVB + vo);
                ldsm4t(vb_l, st + 3 * KVB + vo);
#pragma unroll
                for (int j2 = 0; j2 < 2; j2++) {
                    int jt = g * 2 + j2;
                    mma16816(oacc[jt], a_h, vb_h[j2 * 2], vb_h[j2 * 2 + 1]);
                    mma16816(oacc[jt], a_h, vb_l[j2 * 2], vb_l[j2 * 2 + 1]);
                    mma16816(oacc[jt], a_l, vb_h[j2 * 2], vb_h[j2 * 2 + 1]);
                }
            }
        }
    }

    float inv0 = 1.0f / l0r, inv1 = 1.0f / l1r;
    size_t base0 = (size_t)(b * T_SEQ + qrow0) * DM + h * HD;
    size_t base1 = (size_t)(b * T_SEQ + qrow1) * DM + h * HD;
#pragma unroll
    for (int j = 0; j < 12; j++) {
        int col = j * 8 + (lane & 3) * 2;
        float v0 = oacc[j][0] * inv0, v1 = oacc[j][1] * inv0;
        float v2 = oacc[j][2] * inv1, v3 = oacc[j][3] * inv1;
        __nv_bfloat162 h01 = __floats2bfloat162_rn(v0, v1);
        __nv_bfloat162 h23 = __floats2bfloat162_rn(v2, v3);
        *(__nv_bfloat162*)(ahi + base0 + col) = h01;
        *(__nv_bfloat162*)(ahi + base1 + col) = h23;
        __nv_bfloat162 l01 = __floats2bfloat162_rn(v0 - __low2float(h01), v1 - __high2float(h01));
        __nv_bfloat162 l23 = __floats2bfloat162_rn(v2 - __low2float(h23), v3 - __high2float(h23));
        *(__nv_bfloat162*)(alo + base0 + col) = l01;
        *(__nv_bfloat162*)(alo + base1 + col) = l23;
    }
}

// ======================= launch =======================
extern "C" void kernel_launch(void* const* d_in, const int* in_sizes, int n_in,
                              void* d_out, int out_size) {
    const float* x     = (const float*)d_in[0];
    const float* w_qkv = (const float*)d_in[1];
    const float* w_o   = (const float*)d_in[2];
    const float* Rs    = (const float*)d_in[3];
    float* out = (float*)d_out;

    float* qkv;
    cudaGetSymbolAddress((void**)&qkv, g_qkv);
    __nv_bfloat16 *xhi, *xlo, *wqh, *wql, *woh, *wol, *ahi, *alo;
    cudaGetSymbolAddress((void**)&xhi, g_xhi);
    cudaGetSymbolAddress((void**)&xlo, g_xlo);
    cudaGetSymbolAddress((void**)&wqh, g_wqh);
    cudaGetSymbolAddress((void**)&wql, g_wql);
    cudaGetSymbolAddress((void**)&woh, g_woh);
    cudaGetSymbolAddress((void**)&wol, g_wol);
    cudaGetSymbolAddress((void**)&ahi, g_ahi);
    cudaGetSymbolAddress((void**)&alo, g_alo);
    __nv_bfloat16 *qh, *ql, *kh, *kl, *vh, *vl;
    cudaGetSymbolAddress((void**)&qh, g_qh);
    cudaGetSymbolAddress((void**)&ql, g_ql);
    cudaGetSymbolAddress((void**)&kh, g_kh);
    cudaGetSymbolAddress((void**)&kl, g_kl);
    cudaGetSymbolAddress((void**)&vh, g_vh);
    cudaGetSymbolAddress((void**)&vl, g_vl);

    // 0) bf16 hi/lo splits (vectorized x4)
    {
        int n1 = MROWS * DM / 4, n2 = QKVN * DM / 4, n3 = DM * DM / 4;
        split_bf16<<<(n1 + 255) / 256, 256>>>(x, xhi, xlo, n1);
        split_bf16<<<(n2 + 255) / 256, 256>>>(w_qkv, wqh, wql, n2);
        split_bf16<<<(n3 + 255) / 256, 256>>>(w_o, woh, wol, n3);
    }

    // 1) QKV projection (block 128x256)
    cudaFuncSetAttribute(gemm_hmma3, cudaFuncAttributeMaxDynamicSharedMemorySize, GEMM_SMEM);
    gemm_hmma3<<<dim3(QKVN / 256, MROWS / 128), 256, GEMM_SMEM>>>(
        xhi, xlo, wqh, wql, qkv, MROWS, QKVN, DM);

    // 2) RoPE + scale + split + per-head relayout
    prep_kernel<<<dim3(T_SEQ, BATCH), 256>>>(qkv, Rs, qh, ql, kh, kl, vh, vl);

    // 3) HMMA flash attention -> ahi/alo
    cudaFuncSetAttribute(attn_hmma, cudaFuncAttributeMaxDynamicSharedMemorySize, ATT_SMEM);
    attn_hmma<<<dim3(T_SEQ / 128, BATCH * NH), 256, ATT_SMEM>>>(
        qh, ql, kh, kl, vh, vl, ahi, alo);

    // 4) Out-projection (block 128x256)
    gemm_hmma3<<<dim3(DM / 256, MROWS / 128), 256, GEMM_SMEM>>>(
        ahi, alo, woh, wol, out, MROWS, DM, DM);
}

// round 15
// speedup vs baseline: 1.3353x; 1.0228x over previous
#include <cuda_runtime.h>
#include <cuda_bf16.h>
#include <cstdint>
#include <math.h>

// Problem constants (fixed shapes)
#define T_SEQ 2048
#define BATCH 2
#define DM    1536
#define NH    16
#define HD    96
#define QKVN  4608          // 3 * NH * HD
#define MROWS 4096          // BATCH * T_SEQ
#define NTRIP 32            // HD / 3

// scale * log2(e): fold softmax scale + exp->exp2 conversion into q
#define SCALE_LOG2E 0.14724463267f

// Scratch (device globals: no allocations allowed)
__device__ __align__(128) float g_qkv[(size_t)MROWS * QKVN];

__device__ __align__(128) __nv_bfloat16 g_xhi[(size_t)MROWS * DM];
__device__ __align__(128) __nv_bfloat16 g_xlo[(size_t)MROWS * DM];
__device__ __align__(128) __nv_bfloat16 g_wqh[(size_t)QKVN * DM];
__device__ __align__(128) __nv_bfloat16 g_wql[(size_t)QKVN * DM];
__device__ __align__(128) __nv_bfloat16 g_woh[(size_t)DM * DM];
__device__ __align__(128) __nv_bfloat16 g_wol[(size_t)DM * DM];
__device__ __align__(128) __nv_bfloat16 g_ahi[(size_t)MROWS * DM];
__device__ __align__(128) __nv_bfloat16 g_alo[(size_t)MROWS * DM];

#define BHSZ ((size_t)BATCH * NH * T_SEQ * HD)
__device__ __align__(128) __nv_bfloat16 g_qh[BHSZ];
__device__ __align__(128) __nv_bfloat16 g_ql[BHSZ];
__device__ __align__(128) __nv_bfloat16 g_kh[BHSZ];
__device__ __align__(128) __nv_bfloat16 g_kl[BHSZ];
__device__ __align__(128) __nv_bfloat16 g_vh[BHSZ];
__device__ __align__(128) __nv_bfloat16 g_vl[BHSZ];

// ======================= helpers (base ISA only) =======================
__device__ __forceinline__ uint32_t smem_u32(const void* p) {
    uint32_t a;
    asm("{ .reg .u64 t; cvta.to.shared.u64 t, %1; cvt.u32.u64 %0, t; }" : "=r"(a) : "l"(p));
    return a;
}

__device__ __forceinline__ void cp16(uint32_t saddr, const void* gptr) {
    asm volatile("cp.async.cg.shared.global [%0], [%1], 16;" :: "r"(saddr), "l"(gptr));
}
__device__ __forceinline__ void cp_commit() { asm volatile("cp.async.commit_group;"); }
__device__ __forceinline__ void cp_wait0()  { asm volatile("cp.async.wait_group 0;" ::: "memory"); }
__device__ __forceinline__ void cp_wait1()  { asm volatile("cp.async.wait_group 1;" ::: "memory"); }

__device__ __forceinline__ void ldsm4(uint32_t* r, uint32_t addr) {
    asm volatile("ldmatrix.sync.aligned.m8n8.x4.shared.b16 {%0,%1,%2,%3}, [%4];"
                 : "=r"(r[0]), "=r"(r[1]), "=r"(r[2]), "=r"(r[3]) : "r"(addr));
}
__device__ __forceinline__ void ldsm4t(uint32_t* r, uint32_t addr) {
    asm volatile("ldmatrix.sync.aligned.m8n8.x4.trans.shared.b16 {%0,%1,%2,%3}, [%4];"
                 : "=r"(r[0]), "=r"(r[1]), "=r"(r[2]), "=r"(r[3]) : "r"(addr));
}

__device__ __forceinline__ void mma16816(float* c, const uint32_t* a, uint32_t b0, uint32_t b1) {
    asm volatile(
        "mma.sync.aligned.m16n8k16.row.col.f32.bf16.bf16.f32 "
        "{%0,%1,%2,%3}, {%4,%5,%6,%7}, {%8,%9}, {%0,%1,%2,%3};"
        : "+f"(c[0]), "+f"(c[1]), "+f"(c[2]), "+f"(c[3])
        : "r"(a[0]), "r"(a[1]), "r"(a[2]), "r"(a[3]), "r"(b0), "r"(b1));
}

__device__ __forceinline__ float ex2f(float x) {
    float y;
    asm("ex2.approx.f32 %0, %1;" : "=f"(y) : "f"(x));
    return y;
}

// ======================= bf16x3 HMMA GEMM v4: 128x256 block, 64x64 warp tiles, 3-stage =====
// 8 warps: wm = wid&1 (two 64-row slabs), wn = wid>>1 (four 64-col slabs).
// smem/stage: AH(10240) | AL(10240) | BH(20480) | BL(20480) = 61440 B; 3 stages = 180 KB.
// regs=244 -> 1 CTA/SM regardless of smem, so the 3rd stage is free.
#define GT_STRIDE 40                           // 80B rows: 16B-aligned, conflict-free
#define GV_AH 0
#define GV_AL 10240
#define GV_BH 20480
#define GV_BL 40960
#define GV_STAGE_B 61440
#define GEMM_SMEM (3 * GV_STAGE_B)             // 184320 bytes (<= 227KB/block), 1 CTA/SM

__device__ __forceinline__ void issue_chunk(uint32_t sbase, int stage,
                                            const __nv_bfloat16* Ahi, const __nv_bfloat16* Alo,
                                            const __nv_bfloat16* Bhi, const __nv_bfloat16* Blo,
                                            int K, int m0, int n0, int col0, int tid) {
    uint32_t st = sbase + (uint32_t)stage * GV_STAGE_B;
    // A: 128 rows x 4 chunks of 16B (hi + lo)
#pragma unroll
    for (int i = 0; i < 2; i++) {
        int e = tid + i * 256;       // 0..511
        int row = e >> 2, q = e & 3;
        uint32_t so = (uint32_t)(row * GT_STRIDE + q * 8) * 2;
        size_t go = (size_t)(m0 + row) * K + col0 + q * 8;
        cp16(st + GV_AH + so, Ahi + go);
        cp16(st + GV_AL + so, Alo + go);
    }
    // B: 256 rows x 4 chunks of 16B (hi + lo)
#pragma unroll
    for (int i = 0; i < 4; i++) {
        int e = tid + i * 256;       // 0..1023
        int row = e >> 2, q = e & 3;
        uint32_t so = (uint32_t)(row * GT_STRIDE + q * 8) * 2;
        size_t go = (size_t)(n0 + row) * K + col0 + q * 8;
        cp16(st + GV_BH + so, Bhi + go);
        cp16(st + GV_BL + so, Blo + go);
    }
}

__global__ __launch_bounds__(256, 1) void gemm_hmma3(const __nv_bfloat16* __restrict__ Ahi,
                                                     const __nv_bfloat16* __restrict__ Alo,
                                                     const __nv_bfloat16* __restrict__ Bhi,
                                                     const __nv_bfloat16* __restrict__ Blo,
                                                     float* __restrict__ C,
                                                     int M, int N, int K) {
    extern __shared__ __align__(128) char smem[];
    const uint32_t sbase = smem_u32(smem);
    const int tid = threadIdx.x;
    const int wid = tid >> 5;
    const int lane = tid & 31;
    const int wm = wid & 1;        // 0..1 -> 64-row slab
    const int wn = wid >> 1;       // 0..3 -> 64-col slab
    const int m0 = blockIdx.y * 128;
    const int n0 = blockIdx.x * 256;
    const int nchunk = K / 32;

    float acc[4][8][4];
#pragma unroll
    for (int i = 0; i < 4; i++)
#pragma unroll
        for (int j = 0; j < 8; j++)
#pragma unroll
            for (int q = 0; q < 4; q++) acc[i][j][q] = 0.0f;

    const int ar  = lane & 15;
    const int akb = (lane >> 4) << 3;
    const int br  = (lane & 7) + ((lane >> 4) << 3);
    const int bkb = ((lane >> 3) & 1) << 3;

    // prologue: fill stages 0 and 1
    issue_chunk(sbase, 0, Ahi, Alo, Bhi, Blo, K, m0, n0, 0, tid);
    cp_commit();
    issue_chunk(sbase, 1, Ahi, Alo, Bhi, Blo, K, m0, n0, 32, tid);
    cp_commit();

    for (int c = 0; c < nchunk; c++) {
        if (c + 1 < nchunk) cp_wait1(); else cp_wait0();   // group c landed
        __syncthreads();   // all warps done with stage (c-1)%3 == (c+2)%3
        if (c + 2 < nchunk) {
            issue_chunk(sbase, (c + 2) % 3, Ahi, Alo, Bhi, Blo, K, m0, n0, (c + 2) * 32, tid);
            cp_commit();
        }
        const uint32_t st = sbase + (uint32_t)(c % 3) * GV_STAGE_B;
#pragma unroll
        for (int ks = 0; ks < 2; ks++) {
            uint32_t ah[4][4], al[4][4], bh[4][4], bl[4][4];
#pragma unroll
            for (int i = 0; i < 4; i++) {
                uint32_t ro = (uint32_t)((wm * 64 + i * 16 + ar) * GT_STRIDE + ks * 16 + akb) * 2;
                ldsm4(ah[i], st + GV_AH + ro);
                ldsm4(al[i], st + GV_AL + ro);
            }
#pragma unroll
            for (int p = 0; p < 4; p++) {
                uint32_t ro = (uint32_t)((wn * 64 + p * 16 + br) * GT_STRIDE + ks * 16 + bkb) * 2;
                ldsm4(bh[p], st + GV_BH + ro);
                ldsm4(bl[p], st + GV_BL + ro);
            }
            // pass-major: same-accumulator MMAs spaced 32 apart
#pragma unroll
            for (int i = 0; i < 4; i++)
#pragma unroll
                for (int j = 0; j < 8; j++)
                    mma16816(acc[i][j], ah[i], bh[j >> 1][(j & 1) * 2], bh[j >> 1][(j & 1) * 2 + 1]);
#pragma unroll
            for (int i = 0; i < 4; i++)
#pragma unroll
                for (int j = 0; j < 8; j++)
                    mma16816(acc[i][j], ah[i], bl[j >> 1][(j & 1) * 2], bl[j >> 1][(j & 1) * 2 + 1]);
#pragma unroll
            for (int i = 0; i < 4; i++)
#pragma unroll
                for (int j = 0; j < 8; j++)
                    mma16816(acc[i][j], al[i], bh[j >> 1][(j & 1) * 2], bh[j >> 1][(j & 1) * 2 + 1]);
        }
    }

    const int er = lane >> 2;
    const int ec = (lane & 3) * 2;
#pragma unroll
    for (int i = 0; i < 4; i++) {
        int r0 = m0 + wm * 64 + i * 16 + er;
#pragma unroll
        for (int j = 0; j < 8; j++) {
            int cc = n0 + wn * 64 + j * 8 + ec;
            *(float2*)(C + (size_t)r0 * N + cc)       = make_float2(acc[i][j][0], acc[i][j][1]);
            *(float2*)(C + (size_t)(r0 + 8) * N + cc) = make_float2(acc[i][j][2], acc[i][j][3]);
        }
    }
}

// ======================= fp32 -> bf16 hi/lo split (vectorized x4) =======================
__global__ __launch_bounds__(256) void split_bf16(const float* __restrict__ x,
                                                  __nv_bfloat16* __restrict__ hi,
                                                  __nv_bfloat16* __restrict__ lo, int n4) {
    int i = blockIdx.x * blockDim.x + threadIdx.x;
    if (i >= n4) return;
    float4 v = ((const float4*)x)[i];
    __nv_bfloat162 h01 = __floats2bfloat162_rn(v.x, v.y);
    __nv_bfloat162 h23 = __floats2bfloat162_rn(v.z, v.w);
    __nv_bfloat162 l01 = __floats2bfloat162_rn(v.x - __low2float(h01), v.y - __high2float(h01));
    __nv_bfloat162 l23 = __floats2bfloat162_rn(v.z - __low2float(h23), v.w - __high2float(h23));
    ((uint2*)hi)[i] = make_uint2(*(uint32_t*)&h01, *(uint32_t*)&h23);
    ((uint2*)lo)[i] = make_uint2(*(uint32_t*)&l01, *(uint32_t*)&l23);
}

// ======================= prep: RoPE + scale + split + per-head relayout ==================
__global__ __launch_bounds__(256) void prep_kernel(const float* __restrict__ qkv,
                                                   const float* __restrict__ Rs,
                                                   __nv_bfloat16* __restrict__ qh,
                                                   __nv_bfloat16* __restrict__ ql,
                                                   __nv_bfloat16* __restrict__ kh,
                                                   __nv_bfloat16* __restrict__ kl,
                                                   __nv_bfloat16* __restrict__ vh,
                                                   __nv_bfloat16* __restrict__ vl) {
    __shared__ float sR[NTRIP * 9];
    const int t = blockIdx.x;
    const int b = blockIdx.y;
    const int tid = threadIdx.x;

    for (int i = tid; i < NTRIP * 9; i += 256)
        sR[i] = Rs[(size_t)t * NTRIP * 9 + i];
    __syncthreads();

    const float* row = qkv + (size_t)(b * T_SEQ + t) * QKVN;

    for (int task = tid; task < 2 * NH * NTRIP; task += 256) {
        int trip = task & 31;
        int h = (task >> 5) & 15;
        int which = task >> 9;
        const float* src = row + which * (NH * HD) + h * HD + trip * 3;
        const float* R = sR + trip * 9;
        float x0 = src[0], x1 = src[1], x2 = src[2];
        float y0 = R[0] * x0 + R[1] * x1 + R[2] * x2;
        float y1 = R[3] * x0 + R[4] * x1 + R[5] * x2;
        float y2 = R[6] * x0 + R[7] * x1 + R[8] * x2;
        if (which == 0) { y0 *= SCALE_LOG2E; y1 *= SCALE_LOG2E; y2 *= SCALE_LOG2E; }
        size_t dst = ((size_t)(b * NH + h) * T_SEQ + t) * HD + trip * 3;
        __nv_bfloat16* H = which ? kh : qh;
        __nv_bfloat16* L = which ? kl : ql;
        __nv_bfloat16 h0 = __float2bfloat16(y0);
        __nv_bfloat16 h1 = __float2bfloat16(y1);
        __nv_bfloat16 h2 = __float2bfloat16(y2);
        H[dst + 0] = h0; L[dst + 0] = __float2bfloat16(y0 - __bfloat162float(h0));
        H[dst + 1] = h1; L[dst + 1] = __float2bfloat16(y1 - __bfloat162float(h1));
        H[dst + 2] = h2; L[dst + 2] = __float2bfloat16(y2 - __bfloat162float(h2));
    }

    for (int d = tid; d < NH * HD; d += 256) {
        int h = d / HD, dd = d % HD;
        float v = row[2 * NH * HD + d];
        size_t dst = ((size_t)(b * NH + h) * T_SEQ + t) * HD + dd;
        __nv_bfloat16 hv = __float2bfloat16(v);
        vh[dst] = hv;
        vl[dst] = __float2bfloat16(v - __bfloat162float(hv));
    }
}

// ======================= HMMA flash attention v3 (unchanged from R11/R12) ==================
#define AT_STR 104
#define KVB (64 * AT_STR * 2)
#define KV_STAGE_B (4 * KVB)
#define ATT_SMEM (2 * KV_STAGE_B)

__global__ __launch_bounds__(256) void attn_hmma(const __nv_bfloat16* __restrict__ qh,
                                                 const __nv_bfloat16* __restrict__ ql,
                                                 const __nv_bfloat16* __restrict__ kh,
                                                 const __nv_bfloat16* __restrict__ kl,
                                                 const __nv_bfloat16* __restrict__ vh,
                                                 const __nv_bfloat16* __restrict__ vl,
                                                 __nv_bfloat16* __restrict__ ahi,
                                                 __nv_bfloat16* __restrict__ alo) {
    extern __shared__ __align__(128) char smem[];
    const uint32_t sbase = smem_u32(smem);
    const int tid = threadIdx.x;
    const int wid = tid >> 5;
    const int lane = tid & 31;
    const int qt = gridDim.x - 1 - blockIdx.x;
    const int bh = blockIdx.y;
    const int b = bh >> 4;
    const int h = bh & 15;
    const int q0 = qt * 128;

    const size_t bhoff = (size_t)bh * T_SEQ * HD;
    const __nv_bfloat16* qh_b = qh + bhoff;
    const __nv_bfloat16* ql_b = ql + bhoff;
    const __nv_bfloat16* kh_b = kh + bhoff;
    const __nv_bfloat16* kl_b = kl + bhoff;
    const __nv_bfloat16* vh_b = vh + bhoff;
    const __nv_bfloat16* vl_b = vl + bhoff;

    const uint32_t stage0 = sbase;
    const uint32_t stage1 = sbase + KV_STAGE_B;

#pragma unroll
    for (int i = 0; i < 6; i++) {
        int e = tid + i * 256;
        int row = e / 12, c = e % 12;
        uint32_t so = (uint32_t)(row * AT_STR + c * 8) * 2;
        size_t go = (size_t)(q0 + row) * HD + c * 8;
        cp16(stage1 + so, qh_b + go);
        cp16(stage1 + 2 * KVB + so, ql_b + go);
    }
    cp_commit();   // group: Q

#pragma unroll
    for (int i = 0; i < 3; i++) {
        int e = tid + i * 256;
        int row = e / 12, c = e % 12;
        uint32_t so = (uint32_t)(row * AT_STR + c * 8) * 2;
        size_t go = (size_t)row * HD + c * 8;
        cp16(stage0 + 0 * KVB + so, kh_b + go);
        cp16(stage0 + 1 * KVB + so, kl_b + go);
        cp16(stage0 + 2 * KVB + so, vh_b + go);
        cp16(stage0 + 3 * KVB + so, vl_b + go);
    }
    cp_commit();   // group: KV0

    const int ar  = lane & 15;
    const int akb = (lane >> 4) << 3;
    const int br  = (lane & 7) + ((lane >> 4) << 3);
    const int bkb = ((lane >> 3) & 1) << 3;
    const int vr  = (lane & 7) + (((lane >> 3) & 1) << 3);
    const int vcb = ((lane >> 4) & 1) << 3;

    cp_wait1();
    __syncthreads();
    uint32_t qa_h[6][4], qa_l[6][4];
#pragma unroll
    for (int t = 0; t < 6; t++) {
        uint32_t qo = (uint32_t)((wid * 16 + ar) * AT_STR + t * 16 + akb) * 2;
        ldsm4(qa_h[t], stage1 + qo);
        ldsm4(qa_l[t], stage1 + 2 * KVB + qo);
    }

    float oacc[12][4];
#pragma unroll
    for (int j = 0; j < 12; j++)
#pragma unroll
        for (int q = 0; q < 4; q++) oacc[j][q] = 0.0f;
    float m0r = -1e30f, m1r = -1e30f, l0r = 0.0f, l1r = 0.0f;

    const int ktiles = 2 * (qt + 1);
    const int r0loc = lane >> 2;
    const int qrow0 = q0 + wid * 16 + r0loc;
    const int qrow1 = qrow0 + 8;

    for (int kt = 0; kt < ktiles; kt++) {
        cp_wait0();
        __syncthreads();
        if (kt + 1 < ktiles) {
            uint32_t stn = ((kt + 1) & 1) ? stage1 : stage0;
#pragma unroll
            for (int i = 0; i < 3; i++) {
                int e = tid + i * 256;
                int row = e / 12, c = e % 12;
                uint32_t so = (uint32_t)(row * AT_STR + c * 8) * 2;
                size_t go = (size_t)((kt + 1) * 64 + row) * HD + c * 8;
                cp16(stn + 0 * KVB + so, kh_b + go);
                cp16(stn + 1 * KVB + so, kl_b + go);
                cp16(stn + 2 * KVB + so, vh_b + go);
                cp16(stn + 3 * KVB + so, vl_b + go);
            }
            cp_commit();
        }
        const uint32_t st = (kt & 1) ? stage1 : stage0;

        float sacc[8][4];
#pragma unroll
        for (int j = 0; j < 8; j++)
#pragma unroll
            for (int q = 0; q < 4; q++) sacc[j][q] = 0.0f;

#pragma unroll
        for (int t = 0; t < 6; t++) {
#pragma unroll
            for (int g = 0; g < 4; g++) {
                uint32_t kb_h[4], kb_l[4];
                uint32_t ko = (uint32_t)((g * 16 + br) * AT_STR + t * 16 + bkb) * 2;
                ldsm4(kb_h, st + 0 * KVB + ko);
                ldsm4(kb_l, st + 1 * KVB + ko);
#pragma unroll
                for (int j2 = 0; j2 < 2; j2++) {
                    int j = g * 2 + j2;
                    mma16816(sacc[j], qa_h[t], kb_h[j2 * 2], kb_h[j2 * 2 + 1]);
                    mma16816(sacc[j], qa_h[t], kb_l[j2 * 2], kb_l[j2 * 2 + 1]);
                    mma16816(sacc[j], qa_l[t], kb_h[j2 * 2], kb_h[j2 * 2 + 1]);
                }
            }
        }

        if (kt >= ktiles - 2) {
            int kbase = kt * 64 + (lane & 3) * 2;
#pragma unroll
            for (int j = 0; j < 8; j++) {
                int k0i = kbase + j * 8;
                if (k0i > qrow0)     sacc[j][0] = -1e30f;
                if (k0i + 1 > qrow0) sacc[j][1] = -1e30f;
                if (k0i > qrow1)     sacc[j][2] = -1e30f;
                if (k0i + 1 > qrow1) sacc[j][3] = -1e30f;
            }
        }

        float mx0 = -1e30f, mx1 = -1e30f;
#pragma unroll
        for (int j = 0; j < 8; j++) {
            mx0 = fmaxf(mx0, fmaxf(sacc[j][0], sacc[j][1]));
            mx1 = fmaxf(mx1, fmaxf(sacc[j][2], sacc[j][3]));
        }
        mx0 = fmaxf(mx0, __shfl_xor_sync(0xffffffffu, mx0, 1));
        mx0 = fmaxf(mx0, __shfl_xor_sync(0xffffffffu, mx0, 2));
        mx1 = fmaxf(mx1, __shfl_xor_sync(0xffffffffu, mx1, 1));
        mx1 = fmaxf(mx1, __shfl_xor_sync(0xffffffffu, mx1, 2));
        float mn0 = fmaxf(m0r, mx0), mn1 = fmaxf(m1r, mx1);
        float corr0 = ex2f(m0r - mn0), corr1 = ex2f(m1r - mn1);
        m0r = mn0; m1r = mn1;

        uint32_t pa_h[8][2], pa_l[8][2];
        float rs0 = 0.0f, rs1 = 0.0f;
#pragma unroll
        for (int j = 0; j < 8; j++) {
            float p0 = ex2f(sacc[j][0] - mn0);
            float p1 = ex2f(sacc[j][1] - mn0);
            float p2 = ex2f(sacc[j][2] - mn1);
            float p3 = ex2f(sacc[j][3] - mn1);
            rs0 += p0 + p1; rs1 += p2 + p3;
            __nv_bfloat162 h01 = __floats2bfloat162_rn(p0, p1);
            __nv_bfloat162 h23 = __floats2bfloat162_rn(p2, p3);
            pa_h[j][0] = *(uint32_t*)&h01;
            pa_h[j][1] = *(uint32_t*)&h23;
            __nv_bfloat162 l01 = __floats2bfloat162_rn(p0 - __low2float(h01), p1 - __high2float(h01));
            __nv_bfloat162 l23 = __floats2bfloat162_rn(p2 - __low2float(h23), p3 - __high2float(h23));
            pa_l[j][0] = *(uint32_t*)&l01;
            pa_l[j][1] = *(uint32_t*)&l23;
        }
        rs0 += __shfl_xor_sync(0xffffffffu, rs0, 1);
        rs0 += __shfl_xor_sync(0xffffffffu, rs0, 2);
        rs1 += __shfl_xor_sync(0xffffffffu, rs1, 1);
        rs1 += __shfl_xor_sync(0xffffffffu, rs1, 2);
        l0r = l0r * corr0 + rs0;
        l1r = l1r * corr1 + rs1;
#pragma unroll
        for (int j = 0; j < 12; j++) {
            oacc[j][0] *= corr0; oacc[j][1] *= corr0;
            oacc[j][2] *= corr1; oacc[j][3] *= corr1;
        }

#pragma unroll
        for (int kc = 0; kc < 4; kc++) {
            uint32_t a_h[4] = {pa_h[2 * kc][0], pa_h[2 * kc][1], pa_h[2 * kc + 1][0], pa_h[2 * kc + 1][1]};
            uint32_t a_l[4] = {pa_l[2 * kc][0], pa_l[2 * kc][1], pa_l[2 * kc + 1][0], pa_l[2 * kc + 1][1]};
            uint32_t vrow = (uint32_t)(kc * 16 + vr);
#pragma unroll
            for (int g = 0; g < 6; g++) {
                uint32_t vb_h[4], vb_l[4];
                uint32_t vo = (vrow * AT_STR + g * 16 + vcb) * 2;
                ldsm4t(vb_h, st + 2 * KVB + vo);
                ldsm4t(vb_l, st + 3 * KVB + vo);
#pragma unroll
                for (int j2 = 0; j2 < 2; j2++) {
                    int jt = g * 2 + j2;
                    mma16816(oacc[jt], a_h, vb_h[j2 * 2], vb_h[j2 * 2 + 1]);
                    mma16816(oacc[jt], a_h, vb_l[j2 * 2], vb_l[j2 * 2 + 1]);
                    mma16816(oacc[jt], a_l, vb_h[j2 * 2], vb_h[j2 * 2 + 1]);
                }
            }
        }
    }

    float inv0 = 1.0f / l0r, inv1 = 1.0f / l1r;
    size_t base0 = (size_t)(b * T_SEQ + qrow0) * DM + h * HD;
    size_t base1 = (size_t)(b * T_SEQ + qrow1) * DM + h * HD;
#pragma unroll
    for (int j = 0; j < 12; j++) {
        int col = j * 8 + (lane & 3) * 2;
        float v0 = oacc[j][0] * inv0, v1 = oacc[j][1] * inv0;
        float v2 = oacc[j][2] * inv1, v3 = oacc[j][3] * inv1;
        __nv_bfloat162 h01 = __floats2bfloat162_rn(v0, v1);
        __nv_bfloat162 h23 = __floats2bfloat162_rn(v2, v3);
        *(__nv_bfloat162*)(ahi + base0 + col) = h01;
        *(__nv_bfloat162*)(ahi + base1 + col) = h23;
        __nv_bfloat162 l01 = __floats2bfloat162_rn(v0 - __low2float(h01), v1 - __high2float(h01));
        __nv_bfloat162 l23 = __floats2bfloat162_rn(v2 - __low2float(h23), v3 - __high2float(h23));
        *(__nv_bfloat162*)(alo + base0 + col) = l01;
        *(__nv_bfloat162*)(alo + base1 + col) = l23;
    }
}

// ======================= launch =======================
extern "C" void kernel_launch(void* const* d_in, const int* in_sizes, int n_in,
                              void* d_out, int out_size) {
    const float* x     = (const float*)d_in[0];
    const float* w_qkv = (const float*)d_in[1];
    const float* w_o   = (const float*)d_in[2];
    const float* Rs    = (const float*)d_in[3];
    float* out = (float*)d_out;

    float* qkv;
    cudaGetSymbolAddress((void**)&qkv, g_qkv);
    __nv_bfloat16 *xhi, *xlo, *wqh, *wql, *woh, *wol, *ahi, *alo;
    cudaGetSymbolAddress((void**)&xhi, g_xhi);
    cudaGetSymbolAddress((void**)&xlo, g_xlo);
    cudaGetSymbolAddress((void**)&wqh, g_wqh);
    cudaGetSymbolAddress((void**)&wql, g_wql);
    cudaGetSymbolAddress((void**)&woh, g_woh);
    cudaGetSymbolAddress((void**)&wol, g_wol);
    cudaGetSymbolAddress((void**)&ahi, g_ahi);
    cudaGetSymbolAddress((void**)&alo, g_alo);
    __nv_bfloat16 *qh, *ql, *kh, *kl, *vh, *vl;
    cudaGetSymbolAddress((void**)&qh, g_qh);
    cudaGetSymbolAddress((void**)&ql, g_ql);
    cudaGetSymbolAddress((void**)&kh, g_kh);
    cudaGetSymbolAddress((void**)&kl, g_kl);
    cudaGetSymbolAddress((void**)&vh, g_vh);
    cudaGetSymbolAddress((void**)&vl, g_vl);

    // 0) bf16 hi/lo splits (vectorized x4)
    {
        int n1 = MROWS * DM / 4, n2 = QKVN * DM / 4, n3 = DM * DM / 4;
        split_bf16<<<(n1 + 255) / 256, 256>>>(x, xhi, xlo, n1);
        split_bf16<<<(n2 + 255) / 256, 256>>>(w_qkv, wqh, wql, n2);
        split_bf16<<<(n3 + 255) / 256, 256>>>(w_o, woh, wol, n3);
    }

    // 1) QKV projection (block 128x256, 3-stage)
    cudaFuncSetAttribute(gemm_hmma3, cudaFuncAttributeMaxDynamicSharedMemorySize, GEMM_SMEM);
    gemm_hmma3<<<dim3(QKVN / 256, MROWS / 128), 256, GEMM_SMEM>>>(
        xhi, xlo, wqh, wql, qkv, MROWS, QKVN, DM);

    // 2) RoPE + scale + split + per-head relayout
    prep_kernel<<<dim3(T_SEQ, BATCH), 256>>>(qkv, Rs, qh, ql, kh, kl, vh, vl);

    // 3) HMMA flash attention -> ahi/alo
    cudaFuncSetAttribute(attn_hmma, cudaFuncAttributeMaxDynamicSharedMemorySize, ATT_SMEM);
    attn_hmma<<<dim3(T_SEQ / 128, BATCH * NH), 256, ATT_SMEM>>>(
        qh, ql, kh, kl, vh, vl, ahi, alo);

    // 4) Out-projection (block 128x256, 3-stage)
    gemm_hmma3<<<dim3(DM / 256, MROWS / 128), 256, GEMM_SMEM>>>(
        ahi, alo, woh, wol, out, MROWS, DM, DM);
}